// round 2
// baseline (speedup 1.0000x reference)
#include <cuda_runtime.h>
#include <math.h>

// ---------------- problem constants ----------------
#define TOK    4096   // B*T
#define BATCH  2
#define T_SEQ  2048
#define C_EMB  1024
#define NHEAD  16
#define HD     64
#define NHID   2816

// ---------------- scratch (static device globals; no runtime alloc) -----
__device__ float g_h   [TOK * C_EMB];
__device__ float g_qkv [TOK * 3 * C_EMB];
__device__ float g_y   [TOK * C_EMB];
__device__ float g_x2  [TOK * C_EMB];
__device__ float g_g1  [TOK * NHID];
__device__ float g_g2  [TOK * NHID];
__device__ float g_mm  [TOK * NHID];

// ---------------- rmsnorm: one block per row (1024 elems) ----------------
__global__ void rmsnorm_k(const float* __restrict__ x,
                          const float* __restrict__ sc,
                          float* __restrict__ out) {
    int row = blockIdx.x;
    int t = threadIdx.x;                       // 256 threads, 1 float4 each
    const float4* xr = (const float4*)(x + (size_t)row * C_EMB);
    const float4* s4 = (const float4*)sc;
    float4* o4 = (float4*)(out + (size_t)row * C_EMB);

    float4 v = xr[t];
    float ss = v.x*v.x + v.y*v.y + v.z*v.z + v.w*v.w;
    #pragma unroll
    for (int off = 16; off; off >>= 1)
        ss += __shfl_xor_sync(0xffffffffu, ss, off);

    __shared__ float part[8];
    __shared__ float inv_s;
    if ((t & 31) == 0) part[t >> 5] = ss;
    __syncthreads();
    if (t < 8) {
        float tot = part[t];
        #pragma unroll
        for (int off = 4; off; off >>= 1)
            tot += __shfl_xor_sync(0xffu, tot, off);
        if (t == 0) inv_s = rsqrtf(tot * (1.0f / C_EMB) + 1e-5f);
    }
    __syncthreads();
    float inv = inv_s;
    float4 w = s4[t];
    o4[t] = make_float4(v.x*inv*w.x, v.y*inv*w.y, v.z*inv*w.z, v.w*inv*w.w);
}

// ---------------- generic fp32 SGEMM: C = A[MxK] @ B[KxN] (+ residual) ----
// BM=BN=128, BK=8, 256 threads, 8x8 register micro-tile, double-buffered smem.
template <int EPI>  // 0: plain  1: C = R + A@B
__global__ __launch_bounds__(256)
void sgemm_k(const float* __restrict__ A, const float* __restrict__ B,
             const float* __restrict__ R, float* __restrict__ Cp,
             int M, int N, int K) {
    const int BM = 128, BN = 128, BK = 8;
    __shared__ __align__(16) float As[2][BK][BM];
    __shared__ __align__(16) float Bs[2][BK][BN];

    int tid = threadIdx.x;
    int bx = blockIdx.x, by = blockIdx.y;
    int ty = tid >> 4, tx = tid & 15;

    int aRow = tid >> 1, aCol = (tid & 1) * 4;      // A tile: 128x8, 1 float4/thread
    int bRow = tid >> 5, bCol = (tid & 31) * 4;     // B tile:   8x128, 1 float4/thread

    const float* Aptr = A + (size_t)(by * BM + aRow) * K + aCol;
    const float* Bptr = B + (size_t)bRow * N + bx * BN + bCol;

    float acc[8][8] = {};
    int numTiles = K / BK;

    {   // preload tile 0
        float4 a = *(const float4*)Aptr;
        As[0][aCol + 0][aRow] = a.x; As[0][aCol + 1][aRow] = a.y;
        As[0][aCol + 2][aRow] = a.z; As[0][aCol + 3][aRow] = a.w;
        *(float4*)&Bs[0][bRow][bCol] = *(const float4*)Bptr;
    }
    __syncthreads();

    int cur = 0;
    for (int t = 0; t < numTiles; ++t) {
        float4 an, bn;
        if (t + 1 < numTiles) {
            an = *(const float4*)(Aptr + (size_t)(t + 1) * BK);
            bn = *(const float4*)(Bptr + (size_t)(t + 1) * BK * N);
        }
        #pragma unroll
        for (int k = 0; k < BK; k++) {
            float a[8], b[8];
            #pragma unroll
            for (int i = 0; i < 8; i++) a[i] = As[cur][k][ty * 8 + i];
            #pragma unroll
            for (int j = 0; j < 8; j++) b[j] = Bs[cur][k][tx * 8 + j];
            #pragma unroll
            for (int i = 0; i < 8; i++)
                #pragma unroll
                for (int j = 0; j < 8; j++)
                    acc[i][j] += a[i] * b[j];
        }
        if (t + 1 < numTiles) {
            int nb = cur ^ 1;
            As[nb][aCol + 0][aRow] = an.x; As[nb][aCol + 1][aRow] = an.y;
            As[nb][aCol + 2][aRow] = an.z; As[nb][aCol + 3][aRow] = an.w;
            *(float4*)&Bs[nb][bRow][bCol] = bn;
            __syncthreads();
            cur = nb;
        }
    }

    #pragma unroll
    for (int i = 0; i < 8; i++) {
        size_t row = (size_t)(by * BM + ty * 8 + i);
        float* crow = Cp + row * N + bx * BN + tx * 8;
        #pragma unroll
        for (int j = 0; j < 8; j += 4) {
            float4 v = make_float4(acc[i][j], acc[i][j+1], acc[i][j+2], acc[i][j+3]);
            if (EPI == 1) {
                float4 rr = *(const float4*)(R + row * N + bx * BN + tx * 8 + j);
                v.x += rr.x; v.y += rr.y; v.z += rr.z; v.w += rr.w;
            }
            *(float4*)(crow + j) = v;
        }
    }
}

// ---------------- RoPE in-place on q,k slices of qkv ----------------------
__global__ void rope_k(float* __restrict__ qkv) {
    int row = blockIdx.x;                 // token row 0..4095
    int pos = row & (T_SEQ - 1);          // position within sequence
    int tid = threadIdx.x;                // 512 = 16 heads * 32 pairs
    int hh = tid >> 5, i = tid & 31;
    // theta = 10000^{-2i/64} = 2^{-log2(1e4) * i/32}
    float theta = exp2f(-13.287712379549449f * ((float)i * (1.0f / 32.0f)));
    float ang = (float)pos * theta;
    float s, c;
    sincosf(ang, &s, &c);

    float* q = qkv + (size_t)row * (3 * C_EMB) + hh * HD + 2 * i;
    float* k = q + C_EMB;
    float qe = q[0], qo = q[1];
    q[0] = qe * c - qo * s;  q[1] = qe * s + qo * c;
    float ke = k[0], ko = k[1];
    k[0] = ke * c - ko * s;  k[1] = ke * s + ko * c;
}

// ---------------- flash attention: 1 thread = 1 query row ----------------
// grid: (T/128, B*NHEAD), 128 threads. K/V tiles of 64 keys in smem.
__global__ __launch_bounds__(128)
void attn_k(const float* __restrict__ qkv, const int* __restrict__ ymask,
            float* __restrict__ y) {
    __shared__ __align__(16) float Ksm[64][64];
    __shared__ __align__(16) float Vsm[64][64];
    __shared__ int ym[64];

    int b    = blockIdx.y >> 4;
    int head = blockIdx.y & 15;
    int r    = blockIdx.x * 128 + threadIdx.x;   // query position in sequence
    int trow = b * T_SEQ + r;

    if (threadIdx.x < 64) ym[threadIdx.x] = ymask[b * 64 + threadIdx.x];
    __syncthreads();
    int ymr = (r < 64) ? ym[r] : 0;

    float4 q4[16];
    const float4* qp = (const float4*)(qkv + (size_t)trow * (3*C_EMB) + head * HD);
    #pragma unroll
    for (int i = 0; i < 16; i++) q4[i] = qp[i];

    float4 o4[16];
    #pragma unroll
    for (int i = 0; i < 16; i++) o4[i] = make_float4(0.f, 0.f, 0.f, 0.f);
    float mval = -INFINITY, l = 0.f;

    int ntiles = blockIdx.x * 2 + 2;             // causal: keys <= last q row
    for (int kt = 0; kt < ntiles; kt++) {
        __syncthreads();                         // previous tile fully consumed
        #pragma unroll
        for (int i = 0; i < 8; i++) {            // 1024 float4s, 128 threads
            int f = i * 128 + threadIdx.x;
            int c = f >> 4, d4 = f & 15;
            size_t base = (size_t)(b * T_SEQ + kt * 64 + c) * (3*C_EMB) + head * HD + d4 * 4;
            ((float4*)Ksm)[f] = *(const float4*)(qkv + base + C_EMB);
            ((float4*)Vsm)[f] = *(const float4*)(qkv + base + 2 * C_EMB);
        }
        __syncthreads();

        int gc0 = kt * 64;
        #pragma unroll 1
        for (int c = 0; c < 64; c++) {
            int gc = gc0 + c;
            bool ok = (gc <= r) || (ymr && gc < 64 && ym[gc]);
            if (!ok) continue;

            const float4* kk = (const float4*)Ksm[c];
            float s = 0.f;
            #pragma unroll
            for (int i = 0; i < 16; i++) {
                float4 kv = kk[i];
                s += q4[i].x*kv.x + q4[i].y*kv.y + q4[i].z*kv.z + q4[i].w*kv.w;
            }
            s *= 0.125f;                          // 1/sqrt(64)

            if (s > mval) {                       // rare after warm-up
                float corr = __expf(mval - s);    // exp(-inf)=0 on first hit
                mval = s;
                l *= corr;
                #pragma unroll
                for (int i = 0; i < 16; i++) {
                    o4[i].x *= corr; o4[i].y *= corr;
                    o4[i].z *= corr; o4[i].w *= corr;
                }
            }
            float p = __expf(s - mval);
            l += p;
            const float4* vv = (const float4*)Vsm[c];
            #pragma unroll
            for (int i = 0; i < 16; i++) {
                float4 vw = vv[i];
                o4[i].x += p*vw.x; o4[i].y += p*vw.y;
                o4[i].z += p*vw.z; o4[i].w += p*vw.w;
            }
        }
    }

    float invl = 1.0f / l;
    float4* yo = (float4*)(y + (size_t)trow * C_EMB + head * HD);
    #pragma unroll
    for (int i = 0; i < 16; i++)
        yo[i] = make_float4(o4[i].x*invl, o4[i].y*invl, o4[i].z*invl, o4[i].w*invl);
}

// ---------------- silu(g1) * g2 ----------------
__global__ void silu_mul_k(const float* __restrict__ g1,
                           const float* __restrict__ g2,
                           float* __restrict__ out, int n) {
    int i = blockIdx.x * blockDim.x + threadIdx.x;
    if (i < n) {
        float a = g1[i];
        out[i] = (a / (1.f + __expf(-a))) * g2[i];
    }
}

// ---------------- driver ----------------
extern "C" void kernel_launch(void* const* d_in, const int* in_sizes, int n_in,
                              void* d_out, int out_size) {
    const float* x      = (const float*)d_in[0];
    const int*   ymask  = (const int*)  d_in[1];
    const float* Wqkv   = (const float*)d_in[2];
    const float* Wattn  = (const float*)d_in[3];
    const float* scale1 = (const float*)d_in[4];
    const float* scale2 = (const float*)d_in[5];
    const float* Wfc1   = (const float*)d_in[6];
    const float* Wfc2   = (const float*)d_in[7];
    const float* Wmlp   = (const float*)d_in[8];
    float* out = (float*)d_out;

    float *h, *qkv, *y, *x2, *g1, *g2, *mm;
    cudaGetSymbolAddress((void**)&h,   g_h);
    cudaGetSymbolAddress((void**)&qkv, g_qkv);
    cudaGetSymbolAddress((void**)&y,   g_y);
    cudaGetSymbolAddress((void**)&x2,  g_x2);
    cudaGetSymbolAddress((void**)&g1,  g_g1);
    cudaGetSymbolAddress((void**)&g2,  g_g2);
    cudaGetSymbolAddress((void**)&mm,  g_mm);

    // h = rmsnorm(x, scale1)
    rmsnorm_k<<<TOK, 256>>>(x, scale1, h);
    // qkv = h @ Wqkv
    sgemm_k<0><<<dim3(3*C_EMB/128, TOK/128), 256>>>(h, Wqkv, nullptr, qkv,
                                                    TOK, 3*C_EMB, C_EMB);
    // rope on q,k in place
    rope_k<<<TOK, 512>>>(qkv);
    // y = attention(q,k,v)
    attn_k<<<dim3(T_SEQ/128, BATCH*NHEAD), 128>>>(qkv, ymask, y);
    // x2 = x + y @ Wattn
    sgemm_k<1><<<dim3(C_EMB/128, TOK/128), 256>>>(y, Wattn, x, x2,
                                                  TOK, C_EMB, C_EMB);
    // h = rmsnorm(x2, scale2)
    rmsnorm_k<<<TOK, 256>>>(x2, scale2, h);
    // g1 = h @ Wfc1 ; g2 = h @ Wfc2
    sgemm_k<0><<<dim3(NHID/128, TOK/128), 256>>>(h, Wfc1, nullptr, g1,
                                                 TOK, NHID, C_EMB);
    sgemm_k<0><<<dim3(NHID/128, TOK/128), 256>>>(h, Wfc2, nullptr, g2,
                                                 TOK, NHID, C_EMB);
    // mm = silu(g1) * g2
    int n = TOK * NHID;
    silu_mul_k<<<(n + 255) / 256, 256>>>(g1, g2, mm, n);
    // out = x2 + mm @ Wmlp
    sgemm_k<1><<<dim3(C_EMB/128, TOK/128), 256>>>(mm, Wmlp, x2, out,
                                                  TOK, C_EMB, NHID);
}

// round 7
// speedup vs baseline: 1.8607x; 1.8607x over previous
#include <cuda_runtime.h>
#include <cuda_bf16.h>
#include <cstdint>
#include <math.h>

// ---------------- problem constants ----------------
#define TOK    4096   // B*T
#define BATCH  2
#define T_SEQ  2048
#define C_EMB  1024
#define NHEAD  16
#define HD     64
#define NHID   2816

// ---------------- scratch (static device globals) ----------------
__device__ float g_h   [TOK * C_EMB];
__device__ float g_qkv [TOK * 3 * C_EMB];
__device__ float g_y   [TOK * C_EMB];
__device__ float g_x2  [TOK * C_EMB];
__device__ float g_g12 [TOK * 2 * NHID];          // [fc1 | fc2] fused outputs
__device__ float g_mm  [TOK * NHID];
__device__ __nv_bfloat16 g_abuf[TOK * 3 * NHID];       // activations split
__device__ __nv_bfloat16 g_bbuf[2 * NHID * 3 * C_EMB]; // weights split (N-major)

// ---------------- small helpers ----------------
__device__ __forceinline__ uint32_t smem_to_u32(const void* p) {
    uint32_t a;
    asm("{ .reg .u64 t; cvta.to.shared.u64 t, %1; cvt.u32.u64 %0, t; }"
        : "=r"(a) : "l"(p));
    return a;
}
__device__ __forceinline__ void cpasync16(uint32_t dst, const void* src) {
    asm volatile("cp.async.cg.shared.global [%0], [%1], 16;"
                 :: "r"(dst), "l"(src) : "memory");
}
__device__ __forceinline__ void ldsm_x4(uint32_t* r, uint32_t addr) {
    asm volatile("ldmatrix.sync.aligned.m8n8.x4.shared.b16 {%0,%1,%2,%3}, [%4];"
                 : "=r"(r[0]), "=r"(r[1]), "=r"(r[2]), "=r"(r[3]) : "r"(addr));
}
__device__ __forceinline__ void ldsm_x2(uint32_t* r, uint32_t addr) {
    asm volatile("ldmatrix.sync.aligned.m8n8.x2.shared.b16 {%0,%1}, [%2];"
                 : "=r"(r[0]), "=r"(r[1]) : "r"(addr));
}
__device__ __forceinline__ void mma_bf16(float* d, const uint32_t* a, const uint32_t* b) {
    asm volatile("mma.sync.aligned.m16n8k16.row.col.f32.bf16.bf16.f32 "
                 "{%0,%1,%2,%3}, {%4,%5,%6,%7}, {%8,%9}, {%0,%1,%2,%3};"
                 : "+f"(d[0]), "+f"(d[1]), "+f"(d[2]), "+f"(d[3])
                 : "r"(a[0]), "r"(a[1]), "r"(a[2]), "r"(a[3]), "r"(b[0]), "r"(b[1]));
}

// ============ bf16 warp-mma GEMM: D[M,N] = A'[M,KP] @ B'[N,KP]^T (+R) ======
// CTA 128x128, BK=32, 256 threads, 8 warps (2 M x 4 N), warp tile 64x32.
// 3-stage cp.async pipeline; 64B smem rows, swizzle c16 ^= (row>>1)&3.
#define GSTAGES     3
#define STAGE_BYTES 16384     // A 8KB + B 8KB
#define GSMEM_TOTAL (GSTAGES * STAGE_BYTES)

template <int EPI>   // 0: C = A@B   1: C = R + A@B
__global__ __launch_bounds__(256)
void gemm_mma_k(const __nv_bfloat16* __restrict__ A, const __nv_bfloat16* __restrict__ B,
                const float* __restrict__ R, float* __restrict__ C, int KP) {
    extern __shared__ char smem[];
    uint32_t sbase = smem_to_u32(smem);
    int tid = threadIdx.x, lane = tid & 31, wid = tid >> 5;
    int wm = wid & 1, wn = wid >> 1;              // warp 64x32 tile at (wm*64, wn*32)
    int bx = blockIdx.x, by = blockIdx.y;
    int N = gridDim.x * 128;
    int NC = KP >> 5;                             // K chunks of 32

    const char* Ag = (const char*)(A + (size_t)(by * 128) * KP);
    const char* Bg = (const char*)(B + (size_t)(bx * 128) * KP);
    size_t ld = (size_t)KP * 2;

    auto load_stage = [&](int stg, int c) {
        uint32_t sA = sbase + stg * STAGE_BYTES;
        uint32_t sB = sA + 8192;
        const char* Ac = Ag + (size_t)c * 64;     // 32 elems * 2B
        const char* Bc = Bg + (size_t)c * 64;
        #pragma unroll
        for (int i = 0; i < 2; i++) {             // 512 chunks of 16B each for A,B
            int idx = i * 256 + tid;
            int r = idx >> 2, c16 = idx & 3;
            uint32_t dof = (uint32_t)(r * 64 + ((c16 ^ ((r >> 1) & 3)) << 4));
            cpasync16(sA + dof, Ac + (size_t)r * ld + c16 * 16);
            cpasync16(sB + dof, Bc + (size_t)r * ld + c16 * 16);
        }
    };

    // ldmatrix per-lane row indices
    int aRow = lane & 15;          // A x4: rows m..m+15
    int aHi  = lane >> 4;          // k half (0/1)
    int bRow = lane & 7;           // B x2: rows n..n+7
    int bHi  = (lane >> 3) & 1;

    float acc[4][4][4];
    #pragma unroll
    for (int i = 0; i < 4; i++)
        #pragma unroll
        for (int j = 0; j < 4; j++)
            #pragma unroll
            for (int q = 0; q < 4; q++) acc[i][j][q] = 0.f;

    #pragma unroll
    for (int p = 0; p < GSTAGES; p++) {
        if (p < NC) load_stage(p, p);
        asm volatile("cp.async.commit_group;" ::: "memory");
    }

    for (int c = 0; c < NC; ++c) {
        int s = c % GSTAGES;
        asm volatile("cp.async.wait_group 2;" ::: "memory");
        __syncthreads();

        uint32_t sA = sbase + s * STAGE_BYTES;
        uint32_t sB = sA + 8192;
        #pragma unroll
        for (int ks = 0; ks < 2; ks++) {
            uint32_t af[4][4], bf[4][2];
            #pragma unroll
            for (int i = 0; i < 4; i++) {
                int m = wm * 64 + i * 16 + aRow;
                uint32_t addr = sA + m * 64 + ((((ks * 2 + aHi)) ^ ((m >> 1) & 3)) << 4);
                ldsm_x4(af[i], addr);
            }
            #pragma unroll
            for (int j = 0; j < 4; j++) {
                int n = wn * 32 + j * 8 + bRow;
                uint32_t addr = sB + n * 64 + ((((ks * 2 + bHi)) ^ ((n >> 1) & 3)) << 4);
                ldsm_x2(bf[j], addr);
            }
            #pragma unroll
            for (int i = 0; i < 4; i++)
                #pragma unroll
                for (int j = 0; j < 4; j++)
                    mma_bf16(acc[i][j], af[i], bf[j]);
        }
        __syncthreads();                          // all warps done reading stage s
        int cn = c + GSTAGES;
        if (cn < NC) load_stage(s, cn);
        asm volatile("cp.async.commit_group;" ::: "memory");
    }

    // epilogue: c0,c1 at (m, n..n+1); c2,c3 at (m+8, n..n+1)
    int rowbase = by * 128 + wm * 64 + (lane >> 2);
    int colbase = bx * 128 + wn * 32 + (lane & 3) * 2;
    #pragma unroll
    for (int i = 0; i < 4; i++) {
        #pragma unroll
        for (int j = 0; j < 4; j++) {
            size_t r0 = (size_t)(rowbase + i * 16);
            int n0 = colbase + j * 8;
            float2 v0 = make_float2(acc[i][j][0], acc[i][j][1]);
            float2 v1 = make_float2(acc[i][j][2], acc[i][j][3]);
            if (EPI == 1) {
                const float2* p0 = (const float2*)(R + r0 * N + n0);
                const float2* p1 = (const float2*)(R + (r0 + 8) * N + n0);
                float2 q0 = *p0, q1 = *p1;
                v0.x += q0.x; v0.y += q0.y; v1.x += q1.x; v1.y += q1.y;
            }
            *(float2*)(C + r0 * N + n0)       = v0;
            *(float2*)(C + (r0 + 8) * N + n0) = v1;
        }
    }
}

// ============ fp32 activations [M][K] -> bf16 [M][3K] hi|lo|hi ============
__global__ void split_act_k(const float* __restrict__ in, __nv_bfloat16* __restrict__ out,
                            int K) {
    int m = blockIdx.y;
    int k = blockIdx.x * 256 + threadIdx.x;
    float a = in[(size_t)m * K + k];
    __nv_bfloat16 hi = __float2bfloat16(a);
    __nv_bfloat16 lo = __float2bfloat16(a - __bfloat162float(hi));
    __nv_bfloat16* o = out + (size_t)m * (3 * K);
    o[k] = hi; o[K + k] = lo; o[2 * K + k] = hi;
}

// ===== fp32 W [K][N] -> bf16 [N][3K] hi|hi|lo (transpose via smem tile) ====
__global__ void split_wt_k(const float* __restrict__ W, __nv_bfloat16* __restrict__ out,
                           int K, int N, int nOfs) {
    __shared__ float tile[32][33];
    int k0 = blockIdx.y * 32, n0 = blockIdx.x * 32;
    int tx = threadIdx.x, ty = threadIdx.y;       // (32, 8)
    #pragma unroll
    for (int j = 0; j < 4; j++)
        tile[ty + 8 * j][tx] = W[(size_t)(k0 + ty + 8 * j) * N + n0 + tx];
    __syncthreads();
    #pragma unroll
    for (int j = 0; j < 4; j++) {
        int n = n0 + ty + 8 * j, k = k0 + tx;
        float a = tile[tx][ty + 8 * j];
        __nv_bfloat16 hi = __float2bfloat16(a);
        __nv_bfloat16 lo = __float2bfloat16(a - __bfloat162float(hi));
        __nv_bfloat16* o = out + (size_t)(n + nOfs) * (3 * K);
        o[k] = hi; o[K + k] = hi; o[2 * K + k] = lo;
    }
}

// ---------------- rmsnorm ----------------
__global__ void rmsnorm_k(const float* __restrict__ x,
                          const float* __restrict__ sc,
                          float* __restrict__ out) {
    int row = blockIdx.x;
    int t = threadIdx.x;
    const float4* xr = (const float4*)(x + (size_t)row * C_EMB);
    const float4* s4 = (const float4*)sc;
    float4* o4 = (float4*)(out + (size_t)row * C_EMB);

    float4 v = xr[t];
    float ss = v.x*v.x + v.y*v.y + v.z*v.z + v.w*v.w;
    #pragma unroll
    for (int off = 16; off; off >>= 1) ss += __shfl_xor_sync(0xffffffffu, ss, off);

    __shared__ float part[8];
    __shared__ float inv_s;
    if ((t & 31) == 0) part[t >> 5] = ss;
    __syncthreads();
    if (t < 8) {
        float tot = part[t];
        #pragma unroll
        for (int off = 4; off; off >>= 1) tot += __shfl_xor_sync(0xffu, tot, off);
        if (t == 0) inv_s = rsqrtf(tot * (1.0f / C_EMB) + 1e-5f);
    }
    __syncthreads();
    float inv = inv_s;
    float4 w = s4[t];
    o4[t] = make_float4(v.x*inv*w.x, v.y*inv*w.y, v.z*inv*w.z, v.w*inv*w.w);
}

// ---------------- RoPE in-place on q,k ----------------
__global__ void rope_k(float* __restrict__ qkv) {
    int row = blockIdx.x;
    int pos = row & (T_SEQ - 1);
    int tid = threadIdx.x;
    int hh = tid >> 5, i = tid & 31;
    float theta = exp2f(-13.287712379549449f * ((float)i * (1.0f / 32.0f)));
    float ang = (float)pos * theta;
    float s, c;
    sincosf(ang, &s, &c);
    float* q = qkv + (size_t)row * (3 * C_EMB) + hh * HD + 2 * i;
    float* k = q + C_EMB;
    float qe = q[0], qo = q[1];
    q[0] = qe * c - qo * s;  q[1] = qe * s + qo * c;
    float ke = k[0], ko = k[1];
    k[0] = ke * c - ko * s;  k[1] = ke * s + ko * c;
}

// ---------------- flash attention (1 thread = 1 query row) ----------------
__global__ __launch_bounds__(128)
void attn_k(const float* __restrict__ qkv, const int* __restrict__ ymask,
            float* __restrict__ y) {
    __shared__ __align__(16) float Ksm[64][64];
    __shared__ __align__(16) float Vsm[64][64];
    __shared__ int ym[64];

    int b    = blockIdx.y >> 4;
    int head = blockIdx.y & 15;
    int r    = blockIdx.x * 128 + threadIdx.x;
    int trow = b * T_SEQ + r;

    if (threadIdx.x < 64) ym[threadIdx.x] = ymask[b * 64 + threadIdx.x];
    __syncthreads();
    int ymr = (r < 64) ? ym[r] : 0;

    float4 q4[16];
    const float4* qp = (const float4*)(qkv + (size_t)trow * (3*C_EMB) + head * HD);
    #pragma unroll
    for (int i = 0; i < 16; i++) q4[i] = qp[i];

    float4 o4[16];
    #pragma unroll
    for (int i = 0; i < 16; i++) o4[i] = make_float4(0.f, 0.f, 0.f, 0.f);
    float mval = -INFINITY, l = 0.f;

    int ntiles = blockIdx.x * 2 + 2;
    for (int kt = 0; kt < ntiles; kt++) {
        __syncthreads();
        #pragma unroll
        for (int i = 0; i < 8; i++) {
            int f = i * 128 + threadIdx.x;
            int c = f >> 4, d4 = f & 15;
            size_t base = (size_t)(b * T_SEQ + kt * 64 + c) * (3*C_EMB) + head * HD + d4 * 4;
            ((float4*)Ksm)[f] = *(const float4*)(qkv + base + C_EMB);
            ((float4*)Vsm)[f] = *(const float4*)(qkv + base + 2 * C_EMB);
        }
        __syncthreads();

        int gc0 = kt * 64;
        #pragma unroll 1
        for (int c = 0; c < 64; c++) {
            int gc = gc0 + c;
            bool ok = (gc <= r) || (ymr && gc < 64 && ym[gc]);
            if (!ok) continue;

            const float4* kk = (const float4*)Ksm[c];
            float s = 0.f;
            #pragma unroll
            for (int i = 0; i < 16; i++) {
                float4 kv = kk[i];
                s += q4[i].x*kv.x + q4[i].y*kv.y + q4[i].z*kv.z + q4[i].w*kv.w;
            }
            s *= 0.125f;

            if (s > mval) {
                float corr = __expf(mval - s);
                mval = s;
                l *= corr;
                #pragma unroll
                for (int i = 0; i < 16; i++) {
                    o4[i].x *= corr; o4[i].y *= corr;
                    o4[i].z *= corr; o4[i].w *= corr;
                }
            }
            float p = __expf(s - mval);
            l += p;
            const float4* vv = (const float4*)Vsm[c];
            #pragma unroll
            for (int i = 0; i < 16; i++) {
                float4 vw = vv[i];
                o4[i].x += p*vw.x; o4[i].y += p*vw.y;
                o4[i].z += p*vw.z; o4[i].w += p*vw.w;
            }
        }
    }

    float invl = 1.0f / l;
    float4* yo = (float4*)(y + (size_t)trow * C_EMB + head * HD);
    #pragma unroll
    for (int i = 0; i < 16; i++)
        yo[i] = make_float4(o4[i].x*invl, o4[i].y*invl, o4[i].z*invl, o4[i].w*invl);
}

// ---------------- silu(g1) * g2 from fused [g1|g2] buffer ----------------
__global__ void silu_mul_k(const float* __restrict__ g12, float* __restrict__ out) {
    int m = blockIdx.y;
    int j = blockIdx.x * 256 + threadIdx.x;
    float a = g12[(size_t)m * (2 * NHID) + j];
    float b = g12[(size_t)m * (2 * NHID) + NHID + j];
    out[(size_t)m * NHID + j] = (a / (1.f + __expf(-a))) * b;
}

// ---------------- driver ----------------
extern "C" void kernel_launch(void* const* d_in, const int* in_sizes, int n_in,
                              void* d_out, int out_size) {
    const float* x      = (const float*)d_in[0];
    const int*   ymask  = (const int*)  d_in[1];
    const float* Wqkv   = (const float*)d_in[2];
    const float* Wattn  = (const float*)d_in[3];
    const float* scale1 = (const float*)d_in[4];
    const float* scale2 = (const float*)d_in[5];
    const float* Wfc1   = (const float*)d_in[6];
    const float* Wfc2   = (const float*)d_in[7];
    const float* Wmlp   = (const float*)d_in[8];
    float* out = (float*)d_out;

    float *h, *qkv, *y, *x2, *g12, *mm;
    __nv_bfloat16 *ab, *bb;
    cudaGetSymbolAddress((void**)&h,   g_h);
    cudaGetSymbolAddress((void**)&qkv, g_qkv);
    cudaGetSymbolAddress((void**)&y,   g_y);
    cudaGetSymbolAddress((void**)&x2,  g_x2);
    cudaGetSymbolAddress((void**)&g12, g_g12);
    cudaGetSymbolAddress((void**)&mm,  g_mm);
    cudaGetSymbolAddress((void**)&ab,  g_abuf);
    cudaGetSymbolAddress((void**)&bb,  g_bbuf);

    cudaFuncSetAttribute(gemm_mma_k<0>, cudaFuncAttributeMaxDynamicSharedMemorySize, GSMEM_TOTAL);
    cudaFuncSetAttribute(gemm_mma_k<1>, cudaFuncAttributeMaxDynamicSharedMemorySize, GSMEM_TOTAL);

    dim3 wt8(32, 8);

    // ---- h = rmsnorm(x, scale1);  qkv = h @ Wqkv ----
    rmsnorm_k<<<TOK, 256>>>(x, scale1, h);
    split_act_k<<<dim3(C_EMB/256, TOK), 256>>>(h, ab, C_EMB);
    split_wt_k<<<dim3(3*C_EMB/32, C_EMB/32), wt8>>>(Wqkv, bb, C_EMB, 3*C_EMB, 0);
    gemm_mma_k<0><<<dim3(3*C_EMB/128, TOK/128), 256, GSMEM_TOTAL>>>(ab, bb, nullptr, qkv, 3*C_EMB);

    // ---- rope + attention ----
    rope_k<<<TOK, 512>>>(qkv);
    attn_k<<<dim3(T_SEQ/128, BATCH*NHEAD), 128>>>(qkv, ymask, y);

    // ---- x2 = x + y @ Wattn ----
    split_act_k<<<dim3(C_EMB/256, TOK), 256>>>(y, ab, C_EMB);
    split_wt_k<<<dim3(C_EMB/32, C_EMB/32), wt8>>>(Wattn, bb, C_EMB, C_EMB, 0);
    gemm_mma_k<1><<<dim3(C_EMB/128, TOK/128), 256, GSMEM_TOTAL>>>(ab, bb, x, x2, 3*C_EMB);

    // ---- h = rmsnorm(x2);  g12 = h @ [Wfc1 | Wfc2] ----
    rmsnorm_k<<<TOK, 256>>>(x2, scale2, h);
    split_act_k<<<dim3(C_EMB/256, TOK), 256>>>(h, ab, C_EMB);
    split_wt_k<<<dim3(NHID/32, C_EMB/32), wt8>>>(Wfc1, bb, C_EMB, NHID, 0);
    split_wt_k<<<dim3(NHID/32, C_EMB/32), wt8>>>(Wfc2, bb, C_EMB, NHID, NHID);
    gemm_mma_k<0><<<dim3(2*NHID/128, TOK/128), 256, GSMEM_TOTAL>>>(ab, bb, nullptr, g12, 3*C_EMB);

    // ---- mm = silu(g1)*g2;  out = x2 + mm @ Wmlp ----
    silu_mul_k<<<dim3(NHID/256, TOK), 256>>>(g12, mm);
    split_act_k<<<dim3(NHID/256, TOK), 256>>>(mm, ab, NHID);
    split_wt_k<<<dim3(C_EMB/32, NHID/32), wt8>>>(Wmlp, bb, NHID, C_EMB, 0);
    gemm_mma_k<1><<<dim3(C_EMB/128, TOK/128), 256, GSMEM_TOTAL>>>(ab, bb, x2, out, 3*NHID);
}

// round 8
// speedup vs baseline: 2.9576x; 1.5896x over previous
#include <cuda_runtime.h>
#include <cuda_bf16.h>
#include <cstdint>
#include <math.h>

// ---------------- problem constants ----------------
#define TOK    4096   // B*T
#define BATCH  2
#define T_SEQ  2048
#define C_EMB  1024
#define NHEAD  16
#define HD     64
#define NHID   2816

// ---------------- scratch (static device globals) ----------------
__device__ float g_h   [TOK * C_EMB];
__device__ float g_qkv [TOK * 3 * C_EMB];
__device__ float g_y   [TOK * C_EMB];
__device__ float g_x2  [TOK * C_EMB];
__device__ float g_g12 [TOK * 2 * NHID];
__device__ float g_mm  [TOK * NHID];
__device__ __nv_bfloat16 g_abuf[TOK * 3 * NHID];
__device__ __nv_bfloat16 g_bbuf[2 * NHID * 3 * C_EMB];
__device__ __nv_bfloat16 g_qs [32 * T_SEQ * 192];   // split-rope q
__device__ __nv_bfloat16 g_ks [32 * T_SEQ * 192];   // split-rope k
__device__ __nv_bfloat16 g_vs [32 * T_SEQ * 64];    // bf16 v

// ---------------- small helpers ----------------
__device__ __forceinline__ uint32_t smem_to_u32(const void* p) {
    uint32_t a;
    asm("{ .reg .u64 t; cvta.to.shared.u64 t, %1; cvt.u32.u64 %0, t; }"
        : "=r"(a) : "l"(p));
    return a;
}
__device__ __forceinline__ void cpasync16(uint32_t dst, const void* src) {
    asm volatile("cp.async.cg.shared.global [%0], [%1], 16;"
                 :: "r"(dst), "l"(src) : "memory");
}
__device__ __forceinline__ void ldsm_x4(uint32_t* r, uint32_t addr) {
    asm volatile("ldmatrix.sync.aligned.m8n8.x4.shared.b16 {%0,%1,%2,%3}, [%4];"
                 : "=r"(r[0]), "=r"(r[1]), "=r"(r[2]), "=r"(r[3]) : "r"(addr));
}
__device__ __forceinline__ void ldsm_x4t(uint32_t* r, uint32_t addr) {
    asm volatile("ldmatrix.sync.aligned.m8n8.x4.trans.shared.b16 {%0,%1,%2,%3}, [%4];"
                 : "=r"(r[0]), "=r"(r[1]), "=r"(r[2]), "=r"(r[3]) : "r"(addr));
}
__device__ __forceinline__ void ldsm_x2(uint32_t* r, uint32_t addr) {
    asm volatile("ldmatrix.sync.aligned.m8n8.x2.shared.b16 {%0,%1}, [%2];"
                 : "=r"(r[0]), "=r"(r[1]) : "r"(addr));
}
__device__ __forceinline__ void mma_bf16(float* d, const uint32_t* a, const uint32_t* b) {
    asm volatile("mma.sync.aligned.m16n8k16.row.col.f32.bf16.bf16.f32 "
                 "{%0,%1,%2,%3}, {%4,%5,%6,%7}, {%8,%9}, {%0,%1,%2,%3};"
                 : "+f"(d[0]), "+f"(d[1]), "+f"(d[2]), "+f"(d[3])
                 : "r"(a[0]), "r"(a[1]), "r"(a[2]), "r"(a[3]), "r"(b[0]), "r"(b[1]));
}
__device__ __forceinline__ uint32_t packbf(float lo, float hi) {
    uint32_t d;
    asm("cvt.rn.bf16x2.f32 %0, %1, %2;" : "=r"(d) : "f"(hi), "f"(lo));
    return d;
}

// ============ bf16 warp-mma GEMM (unchanged from R7) ======================
#define GSTAGES     3
#define STAGE_BYTES 16384
#define GSMEM_TOTAL (GSTAGES * STAGE_BYTES)

template <int EPI>
__global__ __launch_bounds__(256)
void gemm_mma_k(const __nv_bfloat16* __restrict__ A, const __nv_bfloat16* __restrict__ B,
                const float* __restrict__ R, float* __restrict__ C, int KP) {
    extern __shared__ char smem[];
    uint32_t sbase = smem_to_u32(smem);
    int tid = threadIdx.x, lane = tid & 31, wid = tid >> 5;
    int wm = wid & 1, wn = wid >> 1;
    int bx = blockIdx.x, by = blockIdx.y;
    int N = gridDim.x * 128;
    int NC = KP >> 5;

    const char* Ag = (const char*)(A + (size_t)(by * 128) * KP);
    const char* Bg = (const char*)(B + (size_t)(bx * 128) * KP);
    size_t ld = (size_t)KP * 2;

    auto load_stage = [&](int stg, int c) {
        uint32_t sA = sbase + stg * STAGE_BYTES;
        uint32_t sB = sA + 8192;
        const char* Ac = Ag + (size_t)c * 64;
        const char* Bc = Bg + (size_t)c * 64;
        #pragma unroll
        for (int i = 0; i < 2; i++) {
            int idx = i * 256 + tid;
            int r = idx >> 2, c16 = idx & 3;
            uint32_t dof = (uint32_t)(r * 64 + ((c16 ^ ((r >> 1) & 3)) << 4));
            cpasync16(sA + dof, Ac + (size_t)r * ld + c16 * 16);
            cpasync16(sB + dof, Bc + (size_t)r * ld + c16 * 16);
        }
    };

    int aRow = lane & 15, aHi = lane >> 4;
    int bRow = lane & 7,  bHi = (lane >> 3) & 1;

    float acc[4][4][4];
    #pragma unroll
    for (int i = 0; i < 4; i++)
        #pragma unroll
        for (int j = 0; j < 4; j++)
            #pragma unroll
            for (int q = 0; q < 4; q++) acc[i][j][q] = 0.f;

    #pragma unroll
    for (int p = 0; p < GSTAGES; p++) {
        if (p < NC) load_stage(p, p);
        asm volatile("cp.async.commit_group;" ::: "memory");
    }

    for (int c = 0; c < NC; ++c) {
        int s = c % GSTAGES;
        asm volatile("cp.async.wait_group 2;" ::: "memory");
        __syncthreads();

        uint32_t sA = sbase + s * STAGE_BYTES;
        uint32_t sB = sA + 8192;
        #pragma unroll
        for (int ks = 0; ks < 2; ks++) {
            uint32_t af[4][4], bf[4][2];
            #pragma unroll
            for (int i = 0; i < 4; i++) {
                int m = wm * 64 + i * 16 + aRow;
                uint32_t addr = sA + m * 64 + ((((ks * 2 + aHi)) ^ ((m >> 1) & 3)) << 4);
                ldsm_x4(af[i], addr);
            }
            #pragma unroll
            for (int j = 0; j < 4; j++) {
                int n = wn * 32 + j * 8 + bRow;
                uint32_t addr = sB + n * 64 + ((((ks * 2 + bHi)) ^ ((n >> 1) & 3)) << 4);
                ldsm_x2(bf[j], addr);
            }
            #pragma unroll
            for (int i = 0; i < 4; i++)
                #pragma unroll
                for (int j = 0; j < 4; j++)
                    mma_bf16(acc[i][j], af[i], bf[j]);
        }
        __syncthreads();
        int cn = c + GSTAGES;
        if (cn < NC) load_stage(s, cn);
        asm volatile("cp.async.commit_group;" ::: "memory");
    }

    int rowbase = by * 128 + wm * 64 + (lane >> 2);
    int colbase = bx * 128 + wn * 32 + (lane & 3) * 2;
    #pragma unroll
    for (int i = 0; i < 4; i++) {
        #pragma unroll
        for (int j = 0; j < 4; j++) {
            size_t r0 = (size_t)(rowbase + i * 16);
            int n0 = colbase + j * 8;
            float2 v0 = make_float2(acc[i][j][0], acc[i][j][1]);
            float2 v1 = make_float2(acc[i][j][2], acc[i][j][3]);
            if (EPI == 1) {
                float2 q0 = *(const float2*)(R + r0 * N + n0);
                float2 q1 = *(const float2*)(R + (r0 + 8) * N + n0);
                v0.x += q0.x; v0.y += q0.y; v1.x += q1.x; v1.y += q1.y;
            }
            *(float2*)(C + r0 * N + n0)       = v0;
            *(float2*)(C + (r0 + 8) * N + n0) = v1;
        }
    }
}

// ============ fp32 activations [M][K] -> bf16 [M][3K] hi|lo|hi ============
__global__ void split_act_k(const float* __restrict__ in, __nv_bfloat16* __restrict__ out,
                            int K) {
    int m = blockIdx.y;
    int k = blockIdx.x * 256 + threadIdx.x;
    float a = in[(size_t)m * K + k];
    __nv_bfloat16 hi = __float2bfloat16(a);
    __nv_bfloat16 lo = __float2bfloat16(a - __bfloat162float(hi));
    __nv_bfloat16* o = out + (size_t)m * (3 * K);
    o[k] = hi; o[K + k] = lo; o[2 * K + k] = hi;
}

// ===== fp32 W [K][N] -> bf16 [N][3K] hi|hi|lo ====
__global__ void split_wt_k(const float* __restrict__ W, __nv_bfloat16* __restrict__ out,
                           int K, int N, int nOfs) {
    __shared__ float tile[32][33];
    int k0 = blockIdx.y * 32, n0 = blockIdx.x * 32;
    int tx = threadIdx.x, ty = threadIdx.y;
    #pragma unroll
    for (int j = 0; j < 4; j++)
        tile[ty + 8 * j][tx] = W[(size_t)(k0 + ty + 8 * j) * N + n0 + tx];
    __syncthreads();
    #pragma unroll
    for (int j = 0; j < 4; j++) {
        int n = n0 + ty + 8 * j, k = k0 + tx;
        float a = tile[tx][ty + 8 * j];
        __nv_bfloat16 hi = __float2bfloat16(a);
        __nv_bfloat16 lo = __float2bfloat16(a - __bfloat162float(hi));
        __nv_bfloat16* o = out + (size_t)(n + nOfs) * (3 * K);
        o[k] = hi; o[K + k] = hi; o[2 * K + k] = lo;
    }
}

// ---------------- rmsnorm ----------------
__global__ void rmsnorm_k(const float* __restrict__ x,
                          const float* __restrict__ sc,
                          float* __restrict__ out) {
    int row = blockIdx.x;
    int t = threadIdx.x;
    const float4* xr = (const float4*)(x + (size_t)row * C_EMB);
    const float4* s4 = (const float4*)sc;
    float4* o4 = (float4*)(out + (size_t)row * C_EMB);

    float4 v = xr[t];
    float ss = v.x*v.x + v.y*v.y + v.z*v.z + v.w*v.w;
    #pragma unroll
    for (int off = 16; off; off >>= 1) ss += __shfl_xor_sync(0xffffffffu, ss, off);

    __shared__ float part[8];
    __shared__ float inv_s;
    if ((t & 31) == 0) part[t >> 5] = ss;
    __syncthreads();
    if (t < 8) {
        float tot = part[t];
        #pragma unroll
        for (int off = 4; off; off >>= 1) tot += __shfl_xor_sync(0xffu, tot, off);
        if (t == 0) inv_s = rsqrtf(tot * (1.0f / C_EMB) + 1e-5f);
    }
    __syncthreads();
    float inv = inv_s;
    float4 w = s4[t];
    o4[t] = make_float4(v.x*inv*w.x, v.y*inv*w.y, v.z*inv*w.z, v.w*inv*w.w);
}

// ======= fused rope + split: qkv fp32 -> qs/ks (bf16 [bh][T][192]), vs ====
__global__ void qksplit_k(const float* __restrict__ qkv,
                          __nv_bfloat16* __restrict__ qs,
                          __nv_bfloat16* __restrict__ ks,
                          __nv_bfloat16* __restrict__ vsp) {
    int row = blockIdx.x;                 // token 0..4095
    int b = row >> 11, t = row & (T_SEQ - 1);
    int tid = threadIdx.x;                // 512
    int hh = tid >> 5, i = tid & 31;
    float theta = exp2f(-13.287712379549449f * ((float)i * (1.0f / 32.0f)));
    float ang = (float)t * theta;
    float s, c;
    sincosf(ang, &s, &c);

    const float* p = qkv + (size_t)row * (3 * C_EMB) + hh * HD + 2 * i;
    float qe = p[0], qo = p[1];
    float ke = p[C_EMB], ko = p[C_EMB + 1];
    float v0 = p[2 * C_EMB], v1 = p[2 * C_EMB + 1];
    float q0 = qe * c - qo * s, q1 = qe * s + qo * c;
    float k0 = ke * c - ko * s, k1 = ke * s + ko * c;

    size_t base = (size_t)(b * NHEAD + hh) * T_SEQ + t;
    __nv_bfloat16* qd = qs + base * 192;
    __nv_bfloat16* kd = ks + base * 192;
    __nv_bfloat16* vd = vsp + base * 64;

    __nv_bfloat16 qh0 = __float2bfloat16(q0);
    __nv_bfloat16 ql0 = __float2bfloat16(q0 - __bfloat162float(qh0));
    __nv_bfloat16 qh1 = __float2bfloat16(q1);
    __nv_bfloat16 ql1 = __float2bfloat16(q1 - __bfloat162float(qh1));
    qd[2*i] = qh0; qd[64 + 2*i] = ql0; qd[128 + 2*i] = qh0;
    qd[2*i+1] = qh1; qd[64 + 2*i+1] = ql1; qd[128 + 2*i+1] = qh1;

    __nv_bfloat16 kh0 = __float2bfloat16(k0);
    __nv_bfloat16 kl0 = __float2bfloat16(k0 - __bfloat162float(kh0));
    __nv_bfloat16 kh1 = __float2bfloat16(k1);
    __nv_bfloat16 kl1 = __float2bfloat16(k1 - __bfloat162float(kh1));
    kd[2*i] = kh0; kd[64 + 2*i] = kh0; kd[128 + 2*i] = kl0;
    kd[2*i+1] = kh1; kd[64 + 2*i+1] = kh1; kd[128 + 2*i+1] = kl1;

    vd[2*i] = __float2bfloat16(v0);
    vd[2*i+1] = __float2bfloat16(v1);
}

// ================= tensor-core flash attention =============================
// grid (32 reversed-bx, 32 bh), 128 thr. Q tile 64 (4 warps x 16 rows),
// K tile 64 keys, double-buffered. Split-192 QK^T, bf16 P@V.
#define A_QS   0
#define A_KS   25600
#define A_VS   76800
#define A_YM   95232
#define ASMEM  95488

__global__ __launch_bounds__(128)
void attn_mma_k(const __nv_bfloat16* __restrict__ qs,
                const __nv_bfloat16* __restrict__ ks,
                const __nv_bfloat16* __restrict__ vs,
                const int* __restrict__ ymask,
                float* __restrict__ y) {
    extern __shared__ char smem[];
    uint32_t sb = smem_to_u32(smem);
    int tid = threadIdx.x, lane = tid & 31, wid = tid >> 5;
    int bx = (gridDim.x - 1) - blockIdx.x;        // heavy CTAs first
    int bh = blockIdx.y;
    int b = bh >> 4, head = bh & 15;
    int* ymsm = (int*)(smem + A_YM);

    const char* qg = (const char*)(qs + ((size_t)bh * T_SEQ + bx * 64) * 192);
    const char* kg = (const char*)(ks + (size_t)bh * T_SEQ * 192);
    const char* vg = (const char*)(vs + (size_t)bh * T_SEQ * 64);

    if (tid < 64) ymsm[tid] = ymask[b * 64 + tid];

    // ---- load Q tile (64 rows x 384B) into Qs [64][200 bf16] ----
    #pragma unroll
    for (int Lb = 0; Lb < 1536; Lb += 128) {
        int L = Lb + tid;
        int r = (L * 2731) >> 16;                 // L / 24
        int c = L - r * 24;
        cpasync16(sb + A_QS + r * 400 + c * 16, qg + (size_t)r * 384 + c * 16);
    }
    asm volatile("cp.async.commit_group;" ::: "memory");

    auto load_kv = [&](int stg, int kt) {
        uint32_t kd = sb + A_KS + stg * 25600;
        uint32_t vd = sb + A_VS + stg * 9216;
        const char* kc = kg + (size_t)(kt * 64) * 384;
        const char* vc = vg + (size_t)(kt * 64) * 128;
        #pragma unroll
        for (int Lb = 0; Lb < 1536; Lb += 128) {
            int L = Lb + tid;
            int r = (L * 2731) >> 16;
            int c = L - r * 24;
            cpasync16(kd + r * 400 + c * 16, kc + (size_t)r * 384 + c * 16);
        }
        #pragma unroll
        for (int Lb = 0; Lb < 512; Lb += 128) {
            int L = Lb + tid;
            int r = L >> 3, c = L & 7;
            cpasync16(vd + r * 144 + c * 16, vc + (size_t)r * 128 + c * 16);
        }
    };

    load_kv(0, 0);
    asm volatile("cp.async.commit_group;" ::: "memory");

    // wait for Q (group age: Q older than kv0) then build Q fragments
    asm volatile("cp.async.wait_group 1;" ::: "memory");
    __syncthreads();
    uint32_t qf[12][4];
    {
        int arow = wid * 16 + (lane & 15);
        int ahi  = lane >> 4;
        #pragma unroll
        for (int kk = 0; kk < 12; kk++) {
            uint32_t addr = sb + A_QS + arow * 400 + (kk * 16 + ahi * 8) * 2;
            ldsm_x4(qf[kk], addr);
        }
    }

    float o[8][4];
    #pragma unroll
    for (int j = 0; j < 8; j++)
        #pragma unroll
        for (int q = 0; q < 4; q++) o[j][q] = 0.f;
    float mA = -1e30f, mB = -1e30f, lA = 0.f, lB = 0.f;

    int rloc = wid * 16 + (lane >> 2);
    int gA = bx * 64 + rloc, gB = gA + 8;
    int ymA = 0, ymB = 0;
    __syncthreads();                              // ymsm visible
    if (bx == 0) { ymA = ymsm[rloc]; ymB = ymsm[rloc + 8]; }

    int ntiles = bx + 1;
    int s = 0;
    for (int kt = 0; kt < ntiles; kt++) {
        if (kt + 1 < ntiles) {
            load_kv(s ^ 1, kt + 1);
            asm volatile("cp.async.commit_group;" ::: "memory");
            asm volatile("cp.async.wait_group 1;" ::: "memory");
        } else {
            asm volatile("cp.async.wait_group 0;" ::: "memory");
        }
        __syncthreads();

        uint32_t kds = sb + A_KS + s * 25600;
        uint32_t vds = sb + A_VS + s * 9216;

        // ---- S = Q' K'^T ----
        float sf[8][4];
        #pragma unroll
        for (int j = 0; j < 8; j++)
            #pragma unroll
            for (int q = 0; q < 4; q++) sf[j][q] = 0.f;

        #pragma unroll
        for (int kk = 0; kk < 12; kk++) {
            uint32_t kb[8][2];
            #pragma unroll
            for (int jp = 0; jp < 4; jp++) {
                int n = jp * 16 + (lane & 7) + ((lane >> 4) & 1) * 8;
                uint32_t addr = kds + n * 400 + (kk * 16 + ((lane >> 3) & 1) * 8) * 2;
                uint32_t rr[4];
                ldsm_x4(rr, addr);
                kb[jp*2][0] = rr[0]; kb[jp*2][1] = rr[1];
                kb[jp*2+1][0] = rr[2]; kb[jp*2+1][1] = rr[3];
            }
            #pragma unroll
            for (int j = 0; j < 8; j++) mma_bf16(sf[j], qf[kk], kb[j]);
        }

        // ---- scale + mask + online softmax ----
        bool diag = (kt == bx);
        int colb = (lane & 3) * 2;
        #pragma unroll
        for (int j = 0; j < 8; j++) {
            #pragma unroll
            for (int c = 0; c < 2; c++) {
                float vA = sf[j][c] * 0.125f;
                float vB = sf[j][c + 2] * 0.125f;
                if (diag) {
                    int gc = kt * 64 + j * 8 + colb + c;
                    int ymc = (bx == 0) ? ymsm[gc & 63] : 0;
                    if (!((gc <= gA) || (ymA && ymc))) vA = -1e30f;
                    if (!((gc <= gB) || (ymB && ymc))) vB = -1e30f;
                }
                sf[j][c] = vA; sf[j][c + 2] = vB;
            }
        }
        float nmA = mA, nmB = mB;
        #pragma unroll
        for (int j = 0; j < 8; j++) {
            nmA = fmaxf(nmA, fmaxf(sf[j][0], sf[j][1]));
            nmB = fmaxf(nmB, fmaxf(sf[j][2], sf[j][3]));
        }
        nmA = fmaxf(nmA, __shfl_xor_sync(0xffffffffu, nmA, 1));
        nmA = fmaxf(nmA, __shfl_xor_sync(0xffffffffu, nmA, 2));
        nmB = fmaxf(nmB, __shfl_xor_sync(0xffffffffu, nmB, 1));
        nmB = fmaxf(nmB, __shfl_xor_sync(0xffffffffu, nmB, 2));

        float corrA = __expf(mA - nmA), corrB = __expf(mB - nmB);
        mA = nmA; mB = nmB;
        float sumA = 0.f, sumB = 0.f;
        #pragma unroll
        for (int j = 0; j < 8; j++) {
            float p0 = __expf(sf[j][0] - nmA);
            float p1 = __expf(sf[j][1] - nmA);
            float p2 = __expf(sf[j][2] - nmB);
            float p3 = __expf(sf[j][3] - nmB);
            sumA += p0 + p1; sumB += p2 + p3;
            sf[j][0] = p0; sf[j][1] = p1; sf[j][2] = p2; sf[j][3] = p3;
        }
        sumA += __shfl_xor_sync(0xffffffffu, sumA, 1);
        sumA += __shfl_xor_sync(0xffffffffu, sumA, 2);
        sumB += __shfl_xor_sync(0xffffffffu, sumB, 1);
        sumB += __shfl_xor_sync(0xffffffffu, sumB, 2);
        lA = lA * corrA + sumA;
        lB = lB * corrB + sumB;
        #pragma unroll
        for (int j = 0; j < 8; j++) {
            o[j][0] *= corrA; o[j][1] *= corrA;
            o[j][2] *= corrB; o[j][3] *= corrB;
        }

        // ---- pack P to bf16 A-fragments ----
        uint32_t pf[4][4];
        #pragma unroll
        for (int kk2 = 0; kk2 < 4; kk2++) {
            int j0 = 2 * kk2, j1 = j0 + 1;
            pf[kk2][0] = packbf(sf[j0][0], sf[j0][1]);
            pf[kk2][1] = packbf(sf[j0][2], sf[j0][3]);
            pf[kk2][2] = packbf(sf[j1][0], sf[j1][1]);
            pf[kk2][3] = packbf(sf[j1][2], sf[j1][3]);
        }

        // ---- O += P @ V ----
        #pragma unroll
        for (int kk2 = 0; kk2 < 4; kk2++) {
            #pragma unroll
            for (int jdp = 0; jdp < 4; jdp++) {
                int key = kk2 * 16 + ((lane >> 3) & 1) * 8 + (lane & 7);
                int dim = (jdp * 2 + (lane >> 4)) * 8;
                uint32_t rr[4];
                ldsm_x4t(rr, vds + key * 144 + dim * 2);
                mma_bf16(o[jdp * 2],     pf[kk2], rr);
                mma_bf16(o[jdp * 2 + 1], pf[kk2], rr + 2);
            }
        }

        __syncthreads();
        s ^= 1;
    }

    // ---- epilogue ----
    float iA = 1.f / lA, iB = 1.f / lB;
    int col0 = head * 64 + (lane & 3) * 2;
    size_t rowA = (size_t)(b * T_SEQ + gA);
    size_t rowB = rowA + 8;
    #pragma unroll
    for (int jd = 0; jd < 8; jd++) {
        *(float2*)(y + rowA * C_EMB + col0 + jd * 8) =
            make_float2(o[jd][0] * iA, o[jd][1] * iA);
        *(float2*)(y + rowB * C_EMB + col0 + jd * 8) =
            make_float2(o[jd][2] * iB, o[jd][3] * iB);
    }
}

// ---------------- silu(g1) * g2 ----------------
__global__ void silu_mul_k(const float* __restrict__ g12, float* __restrict__ out) {
    int m = blockIdx.y;
    int j = blockIdx.x * 256 + threadIdx.x;
    float a = g12[(size_t)m * (2 * NHID) + j];
    float b = g12[(size_t)m * (2 * NHID) + NHID + j];
    out[(size_t)m * NHID + j] = (a / (1.f + __expf(-a))) * b;
}

// ---------------- driver ----------------
extern "C" void kernel_launch(void* const* d_in, const int* in_sizes, int n_in,
                              void* d_out, int out_size) {
    const float* x      = (const float*)d_in[0];
    const int*   ymask  = (const int*)  d_in[1];
    const float* Wqkv   = (const float*)d_in[2];
    const float* Wattn  = (const float*)d_in[3];
    const float* scale1 = (const float*)d_in[4];
    const float* scale2 = (const float*)d_in[5];
    const float* Wfc1   = (const float*)d_in[6];
    const float* Wfc2   = (const float*)d_in[7];
    const float* Wmlp   = (const float*)d_in[8];
    float* out = (float*)d_out;

    float *h, *qkv, *y, *x2, *g12, *mm;
    __nv_bfloat16 *ab, *bb, *qsp, *ksp, *vsp;
    cudaGetSymbolAddress((void**)&h,   g_h);
    cudaGetSymbolAddress((void**)&qkv, g_qkv);
    cudaGetSymbolAddress((void**)&y,   g_y);
    cudaGetSymbolAddress((void**)&x2,  g_x2);
    cudaGetSymbolAddress((void**)&g12, g_g12);
    cudaGetSymbolAddress((void**)&mm,  g_mm);
    cudaGetSymbolAddress((void**)&ab,  g_abuf);
    cudaGetSymbolAddress((void**)&bb,  g_bbuf);
    cudaGetSymbolAddress((void**)&qsp, g_qs);
    cudaGetSymbolAddress((void**)&ksp, g_ks);
    cudaGetSymbolAddress((void**)&vsp, g_vs);

    cudaFuncSetAttribute(gemm_mma_k<0>, cudaFuncAttributeMaxDynamicSharedMemorySize, GSMEM_TOTAL);
    cudaFuncSetAttribute(gemm_mma_k<1>, cudaFuncAttributeMaxDynamicSharedMemorySize, GSMEM_TOTAL);
    cudaFuncSetAttribute(attn_mma_k,    cudaFuncAttributeMaxDynamicSharedMemorySize, ASMEM);

    dim3 wt8(32, 8);

    // ---- h = rmsnorm(x, scale1);  qkv = h @ Wqkv ----
    rmsnorm_k<<<TOK, 256>>>(x, scale1, h);
    split_act_k<<<dim3(C_EMB/256, TOK), 256>>>(h, ab, C_EMB);
    split_wt_k<<<dim3(3*C_EMB/32, C_EMB/32), wt8>>>(Wqkv, bb, C_EMB, 3*C_EMB, 0);
    gemm_mma_k<0><<<dim3(3*C_EMB/128, TOK/128), 256, GSMEM_TOTAL>>>(ab, bb, nullptr, qkv, 3*C_EMB);

    // ---- rope+split -> tensor-core flash attention ----
    qksplit_k<<<TOK, 512>>>(qkv, qsp, ksp, vsp);
    attn_mma_k<<<dim3(T_SEQ/64, BATCH*NHEAD), 128, ASMEM>>>(qsp, ksp, vsp, ymask, y);

    // ---- x2 = x + y @ Wattn ----
    split_act_k<<<dim3(C_EMB/256, TOK), 256>>>(y, ab, C_EMB);
    split_wt_k<<<dim3(C_EMB/32, C_EMB/32), wt8>>>(Wattn, bb, C_EMB, C_EMB, 0);
    gemm_mma_k<1><<<dim3(C_EMB/128, TOK/128), 256, GSMEM_TOTAL>>>(ab, bb, x, x2, 3*C_EMB);

    // ---- h = rmsnorm(x2);  g12 = h @ [Wfc1 | Wfc2] ----
    rmsnorm_k<<<TOK, 256>>>(x2, scale2, h);
    split_act_k<<<dim3(C_EMB/256, TOK), 256>>>(h, ab, C_EMB);
    split_wt_k<<<dim3(NHID/32, C_EMB/32), wt8>>>(Wfc1, bb, C_EMB, NHID, 0);
    split_wt_k<<<dim3(NHID/32, C_EMB/32), wt8>>>(Wfc2, bb, C_EMB, NHID, NHID);
    gemm_mma_k<0><<<dim3(2*NHID/128, TOK/128), 256, GSMEM_TOTAL>>>(ab, bb, nullptr, g12, 3*C_EMB);

    // ---- mm = silu(g1)*g2;  out = x2 + mm @ Wmlp ----
    silu_mul_k<<<dim3(NHID/256, TOK), 256>>>(g12, mm);
    split_act_k<<<dim3(NHID/256, TOK), 256>>>(mm, ab, NHID);
    split_wt_k<<<dim3(C_EMB/32, NHID/32), wt8>>>(Wmlp, bb, NHID, C_EMB, 0);
    gemm_mma_k<1><<<dim3(C_EMB/128, TOK/128), 256, GSMEM_TOTAL>>>(ab, bb, x2, out, 3*NHID);
}

// round 10
// speedup vs baseline: 3.3791x; 1.1425x over previous
#include <cuda_runtime.h>
#include <cuda_bf16.h>
#include <cstdint>
#include <math.h>

// ---------------- problem constants ----------------
#define TOK    4096   // B*T
#define BATCH  2
#define T_SEQ  2048
#define C_EMB  1024
#define NHEAD  16
#define HD     64
#define NHID   2816

// ---------------- scratch (static device globals) ----------------
__device__ float g_qkv [TOK * 3 * C_EMB];
__device__ float g_x2  [TOK * C_EMB];
__device__ float g_g12 [TOK * 2 * NHID];
__device__ __nv_bfloat16 g_abuf[TOK * 3 * NHID];
__device__ __nv_bfloat16 g_bbuf[2 * NHID * 3 * C_EMB];
__device__ __nv_bfloat16 g_qs [32 * T_SEQ * 192];
__device__ __nv_bfloat16 g_ks [32 * T_SEQ * 192];
__device__ __nv_bfloat16 g_vs [32 * T_SEQ * 64];

// ---------------- small helpers ----------------
__device__ __forceinline__ uint32_t smem_to_u32(const void* p) {
    uint32_t a;
    asm("{ .reg .u64 t; cvta.to.shared.u64 t, %1; cvt.u32.u64 %0, t; }"
        : "=r"(a) : "l"(p));
    return a;
}
__device__ __forceinline__ void cpasync16(uint32_t dst, const void* src) {
    asm volatile("cp.async.cg.shared.global [%0], [%1], 16;"
                 :: "r"(dst), "l"(src) : "memory");
}
__device__ __forceinline__ void ldsm_x4(uint32_t* r, uint32_t addr) {
    asm volatile("ldmatrix.sync.aligned.m8n8.x4.shared.b16 {%0,%1,%2,%3}, [%4];"
                 : "=r"(r[0]), "=r"(r[1]), "=r"(r[2]), "=r"(r[3]) : "r"(addr));
}
__device__ __forceinline__ void ldsm_x4t(uint32_t* r, uint32_t addr) {
    asm volatile("ldmatrix.sync.aligned.m8n8.x4.trans.shared.b16 {%0,%1,%2,%3}, [%4];"
                 : "=r"(r[0]), "=r"(r[1]), "=r"(r[2]), "=r"(r[3]) : "r"(addr));
}
__device__ __forceinline__ void ldsm_x2(uint32_t* r, uint32_t addr) {
    asm volatile("ldmatrix.sync.aligned.m8n8.x2.shared.b16 {%0,%1}, [%2];"
                 : "=r"(r[0]), "=r"(r[1]) : "r"(addr));
}
__device__ __forceinline__ void mma_bf16(float* d, const uint32_t* a, const uint32_t* b) {
    asm volatile("mma.sync.aligned.m16n8k16.row.col.f32.bf16.bf16.f32 "
                 "{%0,%1,%2,%3}, {%4,%5,%6,%7}, {%8,%9}, {%0,%1,%2,%3};"
                 : "+f"(d[0]), "+f"(d[1]), "+f"(d[2]), "+f"(d[3])
                 : "r"(a[0]), "r"(a[1]), "r"(a[2]), "r"(a[3]), "r"(b[0]), "r"(b[1]));
}
__device__ __forceinline__ uint32_t packbf(float lo, float hi) {
    uint32_t d;
    asm("cvt.rn.bf16x2.f32 %0, %1, %2;" : "=r"(d) : "f"(hi), "f"(lo));
    return d;
}

// ============ bf16 warp-mma GEMM, BK=64: D = A'[M,KP] @ B'[N,KP]^T (+R) ===
// CTA 128x128, 256 thr, 8 warps (2Mx4N), warp 64x32. 3-stage cp.async.
// Stage: A 128x64 bf16 (16KB) + B 128x64 (16KB). 128B rows, xor-swizzle r&7.
#define GSTAGES     3
#define STAGE_BYTES 32768
#define GSMEM_TOTAL (GSTAGES * STAGE_BYTES)

template <int EPI>
__global__ __launch_bounds__(256)
void gemm_mma_k(const __nv_bfloat16* __restrict__ A, const __nv_bfloat16* __restrict__ B,
                const float* __restrict__ R, float* __restrict__ C, int KP) {
    extern __shared__ char smem[];
    uint32_t sbase = smem_to_u32(smem);
    int tid = threadIdx.x, lane = tid & 31, wid = tid >> 5;
    int wm = wid & 1, wn = wid >> 1;
    int bx = blockIdx.x, by = blockIdx.y;
    int N = gridDim.x * 128;
    int NC = KP >> 6;                             // 64-wide K chunks

    const char* Ag = (const char*)(A + (size_t)(by * 128) * KP);
    const char* Bg = (const char*)(B + (size_t)(bx * 128) * KP);
    size_t ld = (size_t)KP * 2;

    auto load_stage = [&](int stg, int c) {
        uint32_t sA = sbase + stg * STAGE_BYTES;
        uint32_t sB = sA + 16384;
        const char* Ac = Ag + (size_t)c * 128;    // 64 elems * 2B
        const char* Bc = Bg + (size_t)c * 128;
        #pragma unroll
        for (int i = 0; i < 4; i++) {             // 1024 16B chunks each
            int idx = i * 256 + tid;
            int r = idx >> 3, c16 = idx & 7;
            uint32_t dof = (uint32_t)(r * 128 + ((c16 ^ (r & 7)) << 4));
            cpasync16(sA + dof, Ac + (size_t)r * ld + c16 * 16);
            cpasync16(sB + dof, Bc + (size_t)r * ld + c16 * 16);
        }
    };

    int aRow = lane & 15, aHi = lane >> 4;
    int bRow = lane & 7,  bHi = (lane >> 3) & 1;

    float acc[4][4][4];
    #pragma unroll
    for (int i = 0; i < 4; i++)
        #pragma unroll
        for (int j = 0; j < 4; j++)
            #pragma unroll
            for (int q = 0; q < 4; q++) acc[i][j][q] = 0.f;

    #pragma unroll
    for (int p = 0; p < GSTAGES; p++) {
        if (p < NC) load_stage(p, p);
        asm volatile("cp.async.commit_group;" ::: "memory");
    }

    for (int c = 0; c < NC; ++c) {
        int s = c % GSTAGES;
        asm volatile("cp.async.wait_group 2;" ::: "memory");
        __syncthreads();

        uint32_t sA = sbase + s * STAGE_BYTES;
        uint32_t sB = sA + 16384;
        #pragma unroll
        for (int ks = 0; ks < 4; ks++) {
            uint32_t af[4][4], bf[4][2];
            #pragma unroll
            for (int i = 0; i < 4; i++) {
                int m = wm * 64 + i * 16 + aRow;
                uint32_t addr = sA + m * 128 + (((ks * 2 + aHi) ^ (m & 7)) << 4);
                ldsm_x4(af[i], addr);
            }
            #pragma unroll
            for (int j = 0; j < 4; j++) {
                int n = wn * 32 + j * 8 + bRow;
                uint32_t addr = sB + n * 128 + (((ks * 2 + bHi) ^ (n & 7)) << 4);
                ldsm_x2(bf[j], addr);
            }
            #pragma unroll
            for (int i = 0; i < 4; i++)
                #pragma unroll
                for (int j = 0; j < 4; j++)
                    mma_bf16(acc[i][j], af[i], bf[j]);
        }
        __syncthreads();
        int cn = c + GSTAGES;
        if (cn < NC) load_stage(s, cn);
        asm volatile("cp.async.commit_group;" ::: "memory");
    }

    int rowbase = by * 128 + wm * 64 + (lane >> 2);
    int colbase = bx * 128 + wn * 32 + (lane & 3) * 2;
    #pragma unroll
    for (int i = 0; i < 4; i++) {
        #pragma unroll
        for (int j = 0; j < 4; j++) {
            size_t r0 = (size_t)(rowbase + i * 16);
            int n0 = colbase + j * 8;
            float2 v0 = make_float2(acc[i][j][0], acc[i][j][1]);
            float2 v1 = make_float2(acc[i][j][2], acc[i][j][3]);
            if (EPI == 1) {
                float2 q0 = *(const float2*)(R + r0 * N + n0);
                float2 q1 = *(const float2*)(R + (r0 + 8) * N + n0);
                v0.x += q0.x; v0.y += q0.y; v1.x += q1.x; v1.y += q1.y;
            }
            *(float2*)(C + r0 * N + n0)       = v0;
            *(float2*)(C + (r0 + 8) * N + n0) = v1;
        }
    }
}

// ===== fp32 W [K][N] -> bf16 [N][3K] hi|hi|lo ====
__global__ void split_wt_k(const float* __restrict__ W, __nv_bfloat16* __restrict__ out,
                           int K, int N, int nOfs) {
    __shared__ float tile[32][33];
    int k0 = blockIdx.y * 32, n0 = blockIdx.x * 32;
    int tx = threadIdx.x, ty = threadIdx.y;
    #pragma unroll
    for (int j = 0; j < 4; j++)
        tile[ty + 8 * j][tx] = W[(size_t)(k0 + ty + 8 * j) * N + n0 + tx];
    __syncthreads();
    #pragma unroll
    for (int j = 0; j < 4; j++) {
        int n = n0 + ty + 8 * j, k = k0 + tx;
        float a = tile[tx][ty + 8 * j];
        __nv_bfloat16 hi = __float2bfloat16(a);
        __nv_bfloat16 lo = __float2bfloat16(a - __bfloat162float(hi));
        __nv_bfloat16* o = out + (size_t)(n + nOfs) * (3 * K);
        o[k] = hi; o[K + k] = hi; o[2 * K + k] = lo;
    }
}

// ---------- fused rmsnorm + act-split: x fp32 -> ab bf16 [M][3K] hi|lo|hi --
__global__ void rmsnorm_split_k(const float* __restrict__ x,
                                const float* __restrict__ sc,
                                __nv_bfloat16* __restrict__ out) {
    int row = blockIdx.x;
    int t = threadIdx.x;
    const float4* xr = (const float4*)(x + (size_t)row * C_EMB);
    const float4* s4 = (const float4*)sc;

    float4 v = xr[t];
    float ss = v.x*v.x + v.y*v.y + v.z*v.z + v.w*v.w;
    #pragma unroll
    for (int off = 16; off; off >>= 1) ss += __shfl_xor_sync(0xffffffffu, ss, off);

    __shared__ float part[8];
    __shared__ float inv_s;
    if ((t & 31) == 0) part[t >> 5] = ss;
    __syncthreads();
    if (t < 8) {
        float tot = part[t];
        #pragma unroll
        for (int off = 4; off; off >>= 1) tot += __shfl_xor_sync(0xffu, tot, off);
        if (t == 0) inv_s = rsqrtf(tot * (1.0f / C_EMB) + 1e-5f);
    }
    __syncthreads();
    float inv = inv_s;
    float4 w = s4[t];
    float a0 = v.x*inv*w.x, a1 = v.y*inv*w.y, a2 = v.z*inv*w.z, a3 = v.w*inv*w.w;

    __nv_bfloat16 h0 = __float2bfloat16(a0), h1 = __float2bfloat16(a1);
    __nv_bfloat16 h2 = __float2bfloat16(a2), h3 = __float2bfloat16(a3);
    uint2 hi = make_uint2(packbf(a0, a1), packbf(a2, a3));
    uint2 lo = make_uint2(packbf(a0 - __bfloat162float(h0), a1 - __bfloat162float(h1)),
                          packbf(a2 - __bfloat162float(h2), a3 - __bfloat162float(h3)));
    char* o = (char*)(out + (size_t)row * (3 * C_EMB));
    *(uint2*)(o + t * 8)                = hi;
    *(uint2*)(o + C_EMB * 2 + t * 8)    = lo;
    *(uint2*)(o + 2 * C_EMB * 2 + t * 8)= hi;
}

// ------- fused silu-mul + act-split: g12 -> ab bf16 [M][3*NHID] ----------
__global__ void silu_split_k(const float* __restrict__ g12,
                             __nv_bfloat16* __restrict__ out) {
    int m = blockIdx.y;
    int j = blockIdx.x * 256 + threadIdx.x;
    float a = g12[(size_t)m * (2 * NHID) + j];
    float b = g12[(size_t)m * (2 * NHID) + NHID + j];
    float v = (a / (1.f + __expf(-a))) * b;
    __nv_bfloat16 hi = __float2bfloat16(v);
    __nv_bfloat16 lo = __float2bfloat16(v - __bfloat162float(hi));
    __nv_bfloat16* o = out + (size_t)m * (3 * NHID);
    o[j] = hi; o[NHID + j] = lo; o[2 * NHID + j] = hi;
}

// ======= fused rope + split: qkv fp32 -> qs/ks (bf16 [bh][T][192]), vs ====
__global__ void qksplit_k(const float* __restrict__ qkv,
                          __nv_bfloat16* __restrict__ qs,
                          __nv_bfloat16* __restrict__ ks,
                          __nv_bfloat16* __restrict__ vsp) {
    int row = blockIdx.x;
    int b = row >> 11, t = row & (T_SEQ - 1);
    int tid = threadIdx.x;
    int hh = tid >> 5, i = tid & 31;
    float theta = exp2f(-13.287712379549449f * ((float)i * (1.0f / 32.0f)));
    float ang = (float)t * theta;
    float s, c;
    sincosf(ang, &s, &c);

    const float* p = qkv + (size_t)row * (3 * C_EMB) + hh * HD + 2 * i;
    float qe = p[0], qo = p[1];
    float ke = p[C_EMB], ko = p[C_EMB + 1];
    float v0 = p[2 * C_EMB], v1 = p[2 * C_EMB + 1];
    float q0 = qe * c - qo * s, q1 = qe * s + qo * c;
    float k0 = ke * c - ko * s, k1 = ke * s + ko * c;

    size_t base = (size_t)(b * NHEAD + hh) * T_SEQ + t;
    __nv_bfloat16* qd = qs + base * 192;
    __nv_bfloat16* kd = ks + base * 192;
    __nv_bfloat16* vd = vsp + base * 64;

    __nv_bfloat16 qh0 = __float2bfloat16(q0);
    __nv_bfloat16 ql0 = __float2bfloat16(q0 - __bfloat162float(qh0));
    __nv_bfloat16 qh1 = __float2bfloat16(q1);
    __nv_bfloat16 ql1 = __float2bfloat16(q1 - __bfloat162float(qh1));
    qd[2*i] = qh0; qd[64 + 2*i] = ql0; qd[128 + 2*i] = qh0;
    qd[2*i+1] = qh1; qd[64 + 2*i+1] = ql1; qd[128 + 2*i+1] = qh1;

    __nv_bfloat16 kh0 = __float2bfloat16(k0);
    __nv_bfloat16 kl0 = __float2bfloat16(k0 - __bfloat162float(kh0));
    __nv_bfloat16 kh1 = __float2bfloat16(k1);
    __nv_bfloat16 kl1 = __float2bfloat16(k1 - __bfloat162float(kh1));
    kd[2*i] = kh0; kd[64 + 2*i] = kh0; kd[128 + 2*i] = kl0;
    kd[2*i+1] = kh1; kd[64 + 2*i+1] = kh1; kd[128 + 2*i+1] = kl1;

    vd[2*i] = __float2bfloat16(v0);
    vd[2*i+1] = __float2bfloat16(v1);
}

// ================= tensor-core flash attention =============================
// Writes the [M][3*C_EMB] hi|lo|hi split of y directly (feeds attn-proj GEMM).
#define A_QS   0
#define A_KS   25600
#define A_VS   76800
#define A_YM   95232
#define ASMEM  95488

__global__ __launch_bounds__(128)
void attn_mma_k(const __nv_bfloat16* __restrict__ qs,
                const __nv_bfloat16* __restrict__ ks,
                const __nv_bfloat16* __restrict__ vs,
                const int* __restrict__ ymask,
                __nv_bfloat16* __restrict__ yab) {
    extern __shared__ char smem[];
    uint32_t sb = smem_to_u32(smem);
    int tid = threadIdx.x, lane = tid & 31, wid = tid >> 5;
    int bx = (gridDim.x - 1) - blockIdx.x;
    int bh = blockIdx.y;
    int b = bh >> 4, head = bh & 15;
    int* ymsm = (int*)(smem + A_YM);

    const char* qg = (const char*)(qs + ((size_t)bh * T_SEQ + bx * 64) * 192);
    const char* kg = (const char*)(ks + (size_t)bh * T_SEQ * 192);
    const char* vg = (const char*)(vs + (size_t)bh * T_SEQ * 64);

    if (tid < 64) ymsm[tid] = ymask[b * 64 + tid];

    #pragma unroll
    for (int Lb = 0; Lb < 1536; Lb += 128) {
        int L = Lb + tid;
        int r = (L * 2731) >> 16;
        int c = L - r * 24;
        cpasync16(sb + A_QS + r * 400 + c * 16, qg + (size_t)r * 384 + c * 16);
    }
    asm volatile("cp.async.commit_group;" ::: "memory");

    auto load_kv = [&](int stg, int kt) {
        uint32_t kd = sb + A_KS + stg * 25600;
        uint32_t vd = sb + A_VS + stg * 9216;
        const char* kc = kg + (size_t)(kt * 64) * 384;
        const char* vc = vg + (size_t)(kt * 64) * 128;
        #pragma unroll
        for (int Lb = 0; Lb < 1536; Lb += 128) {
            int L = Lb + tid;
            int r = (L * 2731) >> 16;
            int c = L - r * 24;
            cpasync16(kd + r * 400 + c * 16, kc + (size_t)r * 384 + c * 16);
        }
        #pragma unroll
        for (int Lb = 0; Lb < 512; Lb += 128) {
            int L = Lb + tid;
            int r = L >> 3, c = L & 7;
            cpasync16(vd + r * 144 + c * 16, vc + (size_t)r * 128 + c * 16);
        }
    };

    load_kv(0, 0);
    asm volatile("cp.async.commit_group;" ::: "memory");

    asm volatile("cp.async.wait_group 1;" ::: "memory");
    __syncthreads();
    uint32_t qf[12][4];
    {
        int arow = wid * 16 + (lane & 15);
        int ahi  = lane >> 4;
        #pragma unroll
        for (int kk = 0; kk < 12; kk++) {
            uint32_t addr = sb + A_QS + arow * 400 + (kk * 16 + ahi * 8) * 2;
            ldsm_x4(qf[kk], addr);
        }
    }

    float o[8][4];
    #pragma unroll
    for (int j = 0; j < 8; j++)
        #pragma unroll
        for (int q = 0; q < 4; q++) o[j][q] = 0.f;
    float mA = -1e30f, mB = -1e30f, lA = 0.f, lB = 0.f;

    int rloc = wid * 16 + (lane >> 2);
    int gA = bx * 64 + rloc, gB = gA + 8;
    int ymA = 0, ymB = 0;
    __syncthreads();
    if (bx == 0) { ymA = ymsm[rloc]; ymB = ymsm[rloc + 8]; }

    int ntiles = bx + 1;
    int s = 0;
    for (int kt = 0; kt < ntiles; kt++) {
        if (kt + 1 < ntiles) {
            load_kv(s ^ 1, kt + 1);
            asm volatile("cp.async.commit_group;" ::: "memory");
            asm volatile("cp.async.wait_group 1;" ::: "memory");
        } else {
            asm volatile("cp.async.wait_group 0;" ::: "memory");
        }
        __syncthreads();

        uint32_t kds = sb + A_KS + s * 25600;
        uint32_t vds = sb + A_VS + s * 9216;

        float sf[8][4];
        #pragma unroll
        for (int j = 0; j < 8; j++)
            #pragma unroll
            for (int q = 0; q < 4; q++) sf[j][q] = 0.f;

        #pragma unroll
        for (int kk = 0; kk < 12; kk++) {
            uint32_t kb[8][2];
            #pragma unroll
            for (int jp = 0; jp < 4; jp++) {
                int n = jp * 16 + (lane & 7) + ((lane >> 4) & 1) * 8;
                uint32_t addr = kds + n * 400 + (kk * 16 + ((lane >> 3) & 1) * 8) * 2;
                uint32_t rr[4];
                ldsm_x4(rr, addr);
                kb[jp*2][0] = rr[0]; kb[jp*2][1] = rr[1];
                kb[jp*2+1][0] = rr[2]; kb[jp*2+1][1] = rr[3];
            }
            #pragma unroll
            for (int j = 0; j < 8; j++) mma_bf16(sf[j], qf[kk], kb[j]);
        }

        bool diag = (kt == bx);
        int colb = (lane & 3) * 2;
        #pragma unroll
        for (int j = 0; j < 8; j++) {
            #pragma unroll
            for (int c = 0; c < 2; c++) {
                float vA = sf[j][c] * 0.125f;
                float vB = sf[j][c + 2] * 0.125f;
                if (diag) {
                    int gc = kt * 64 + j * 8 + colb + c;
                    int ymc = (bx == 0) ? ymsm[gc & 63] : 0;
                    if (!((gc <= gA) || (ymA && ymc))) vA = -1e30f;
                    if (!((gc <= gB) || (ymB && ymc))) vB = -1e30f;
                }
                sf[j][c] = vA; sf[j][c + 2] = vB;
            }
        }
        float nmA = mA, nmB = mB;
        #pragma unroll
        for (int j = 0; j < 8; j++) {
            nmA = fmaxf(nmA, fmaxf(sf[j][0], sf[j][1]));
            nmB = fmaxf(nmB, fmaxf(sf[j][2], sf[j][3]));
        }
        nmA = fmaxf(nmA, __shfl_xor_sync(0xffffffffu, nmA, 1));
        nmA = fmaxf(nmA, __shfl_xor_sync(0xffffffffu, nmA, 2));
        nmB = fmaxf(nmB, __shfl_xor_sync(0xffffffffu, nmB, 1));
        nmB = fmaxf(nmB, __shfl_xor_sync(0xffffffffu, nmB, 2));

        float corrA = __expf(mA - nmA), corrB = __expf(mB - nmB);
        mA = nmA; mB = nmB;
        float sumA = 0.f, sumB = 0.f;
        #pragma unroll
        for (int j = 0; j < 8; j++) {
            float p0 = __expf(sf[j][0] - nmA);
            float p1 = __expf(sf[j][1] - nmA);
            float p2 = __expf(sf[j][2] - nmB);
            float p3 = __expf(sf[j][3] - nmB);
            sumA += p0 + p1; sumB += p2 + p3;
            sf[j][0] = p0; sf[j][1] = p1; sf[j][2] = p2; sf[j][3] = p3;
        }
        sumA += __shfl_xor_sync(0xffffffffu, sumA, 1);
        sumA += __shfl_xor_sync(0xffffffffu, sumA, 2);
        sumB += __shfl_xor_sync(0xffffffffu, sumB, 1);
        sumB += __shfl_xor_sync(0xffffffffu, sumB, 2);
        lA = lA * corrA + sumA;
        lB = lB * corrB + sumB;
        #pragma unroll
        for (int j = 0; j < 8; j++) {
            o[j][0] *= corrA; o[j][1] *= corrA;
            o[j][2] *= corrB; o[j][3] *= corrB;
        }

        uint32_t pf[4][4];
        #pragma unroll
        for (int kk2 = 0; kk2 < 4; kk2++) {
            int j0 = 2 * kk2, j1 = j0 + 1;
            pf[kk2][0] = packbf(sf[j0][0], sf[j0][1]);
            pf[kk2][1] = packbf(sf[j0][2], sf[j0][3]);
            pf[kk2][2] = packbf(sf[j1][0], sf[j1][1]);
            pf[kk2][3] = packbf(sf[j1][2], sf[j1][3]);
        }

        #pragma unroll
        for (int kk2 = 0; kk2 < 4; kk2++) {
            #pragma unroll
            for (int jdp = 0; jdp < 4; jdp++) {
                int key = kk2 * 16 + ((lane >> 3) & 1) * 8 + (lane & 7);
                int dim = (jdp * 2 + (lane >> 4)) * 8;
                uint32_t rr[4];
                ldsm_x4t(rr, vds + key * 144 + dim * 2);
                mma_bf16(o[jdp * 2],     pf[kk2], rr);
                mma_bf16(o[jdp * 2 + 1], pf[kk2], rr + 2);
            }
        }

        __syncthreads();
        s ^= 1;
    }

    // ---- epilogue: write hi|lo|hi split of y directly ----
    float iA = 1.f / lA, iB = 1.f / lB;
    int col0 = head * 64 + (lane & 3) * 2;
    size_t rowA = (size_t)(b * T_SEQ + gA);
    size_t rowB = rowA + 8;
    #pragma unroll
    for (int jd = 0; jd < 8; jd++) {
        float a0 = o[jd][0] * iA, a1 = o[jd][1] * iA;
        float b0 = o[jd][2] * iB, b1 = o[jd][3] * iB;
        __nv_bfloat16 ha0 = __float2bfloat16(a0), ha1 = __float2bfloat16(a1);
        __nv_bfloat16 hb0 = __float2bfloat16(b0), hb1 = __float2bfloat16(b1);
        uint32_t hiA = packbf(a0, a1), hiB = packbf(b0, b1);
        uint32_t loA = packbf(a0 - __bfloat162float(ha0), a1 - __bfloat162float(ha1));
        uint32_t loB = packbf(b0 - __bfloat162float(hb0), b1 - __bfloat162float(hb1));
        uint32_t* pA = (uint32_t*)(yab + rowA * (3 * C_EMB) + col0 + jd * 8);
        uint32_t* pB = (uint32_t*)(yab + rowB * (3 * C_EMB) + col0 + jd * 8);
        pA[0] = hiA; pA[C_EMB / 2] = loA; pA[C_EMB] = hiA;
        pB[0] = hiB; pB[C_EMB / 2] = loB; pB[C_EMB] = hiB;
    }
}

// ---------------- driver ----------------
extern "C" void kernel_launch(void* const* d_in, const int* in_sizes, int n_in,
                              void* d_out, int out_size) {
    const float* x      = (const float*)d_in[0];
    const int*   ymask  = (const int*)  d_in[1];
    const float* Wqkv   = (const float*)d_in[2];
    const float* Wattn  = (const float*)d_in[3];
    const float* scale1 = (const float*)d_in[4];
    const float* scale2 = (const float*)d_in[5];
    const float* Wfc1   = (const float*)d_in[6];
    const float* Wfc2   = (const float*)d_in[7];
    const float* Wmlp   = (const float*)d_in[8];
    float* out = (float*)d_out;

    float *qkv, *x2, *g12;
    __nv_bfloat16 *ab, *bb, *qsp, *ksp, *vsp;
    cudaGetSymbolAddress((void**)&qkv, g_qkv);
    cudaGetSymbolAddress((void**)&x2,  g_x2);
    cudaGetSymbolAddress((void**)&g12, g_g12);
    cudaGetSymbolAddress((void**)&ab,  g_abuf);
    cudaGetSymbolAddress((void**)&bb,  g_bbuf);
    cudaGetSymbolAddress((void**)&qsp, g_qs);
    cudaGetSymbolAddress((void**)&ksp, g_ks);
    cudaGetSymbolAddress((void**)&vsp, g_vs);

    cudaFuncSetAttribute(gemm_mma_k<0>, cudaFuncAttributeMaxDynamicSharedMemorySize, GSMEM_TOTAL);
    cudaFuncSetAttribute(gemm_mma_k<1>, cudaFuncAttributeMaxDynamicSharedMemorySize, GSMEM_TOTAL);
    cudaFuncSetAttribute(attn_mma_k,    cudaFuncAttributeMaxDynamicSharedMemorySize, ASMEM);

    dim3 wt8(32, 8);

    // ---- ab = split(rmsnorm(x));  qkv = ab @ Wqkv' ----
    rmsnorm_split_k<<<TOK, 256>>>(x, scale1, ab);
    split_wt_k<<<dim3(3*C_EMB/32, C_EMB/32), wt8>>>(Wqkv, bb, C_EMB, 3*C_EMB, 0);
    gemm_mma_k<0><<<dim3(3*C_EMB/128, TOK/128), 256, GSMEM_TOTAL>>>(ab, bb, nullptr, qkv, 3*C_EMB);

    // ---- rope+split -> attention (writes split of y into ab) ----
    qksplit_k<<<TOK, 512>>>(qkv, qsp, ksp, vsp);
    attn_mma_k<<<dim3(T_SEQ/64, BATCH*NHEAD), 128, ASMEM>>>(qsp, ksp, vsp, ymask, ab);

    // ---- x2 = x + y @ Wattn ----
    split_wt_k<<<dim3(C_EMB/32, C_EMB/32), wt8>>>(Wattn, bb, C_EMB, C_EMB, 0);
    gemm_mma_k<1><<<dim3(C_EMB/128, TOK/128), 256, GSMEM_TOTAL>>>(ab, bb, x, x2, 3*C_EMB);

    // ---- ab = split(rmsnorm(x2));  g12 = ab @ [Wfc1|Wfc2]' ----
    rmsnorm_split_k<<<TOK, 256>>>(x2, scale2, ab);
    split_wt_k<<<dim3(NHID/32, C_EMB/32), wt8>>>(Wfc1, bb, C_EMB, NHID, 0);
    split_wt_k<<<dim3(NHID/32, C_EMB/32), wt8>>>(Wfc2, bb, C_EMB, NHID, NHID);
    gemm_mma_k<0><<<dim3(2*NHID/128, TOK/128), 256, GSMEM_TOTAL>>>(ab, bb, nullptr, g12, 3*C_EMB);

    // ---- ab = split(silu(g1)*g2);  out = x2 + ab @ Wmlp' ----
    silu_split_k<<<dim3(NHID/256, TOK), 256>>>(g12, ab);
    split_wt_k<<<dim3(C_EMB/32, NHID/32), wt8>>>(Wmlp, bb, NHID, C_EMB, 0);
    gemm_mma_k<1><<<dim3(C_EMB/128, TOK/128), 256, GSMEM_TOTAL>>>(ab, bb, x2, out, 3*NHID);
}

// round 12
// speedup vs baseline: 4.9024x; 1.4508x over previous
#include <cuda_runtime.h>
#include <cuda_fp16.h>
#include <cstdint>
#include <math.h>

// ---------------- problem constants ----------------
#define TOK    4096   // B*T
#define BATCH  2
#define T_SEQ  2048
#define C_EMB  1024
#define NHEAD  16
#define HD     64
#define NHID   2816

// ---------------- scratch (static device globals) ----------------
__device__ float g_qkv [TOK * 3 * C_EMB];
__device__ float g_x2  [TOK * C_EMB];
__device__ float g_g12 [TOK * 2 * NHID];
__device__ __half g_abuf[TOK * 2 * NHID];        // activation 2-term splits
__device__ __half g_bbuf[2 * NHID * C_EMB];      // weights plain fp16 (N-major)
__device__ __half g_qs [32 * T_SEQ * 128];       // q 2-term split
__device__ __half g_ks [32 * T_SEQ * 64];        // k plain fp16
__device__ __half g_vs [32 * T_SEQ * 64];        // v fp16

// ---------------- small helpers ----------------
__device__ __forceinline__ uint32_t smem_to_u32(const void* p) {
    uint32_t a;
    asm("{ .reg .u64 t; cvta.to.shared.u64 t, %1; cvt.u32.u64 %0, t; }"
        : "=r"(a) : "l"(p));
    return a;
}
__device__ __forceinline__ void cpasync16(uint32_t dst, const void* src) {
    asm volatile("cp.async.cg.shared.global [%0], [%1], 16;"
                 :: "r"(dst), "l"(src) : "memory");
}
__device__ __forceinline__ void ldsm_x4(uint32_t* r, uint32_t addr) {
    asm volatile("ldmatrix.sync.aligned.m8n8.x4.shared.b16 {%0,%1,%2,%3}, [%4];"
                 : "=r"(r[0]), "=r"(r[1]), "=r"(r[2]), "=r"(r[3]) : "r"(addr));
}
__device__ __forceinline__ void ldsm_x4t(uint32_t* r, uint32_t addr) {
    asm volatile("ldmatrix.sync.aligned.m8n8.x4.trans.shared.b16 {%0,%1,%2,%3}, [%4];"
                 : "=r"(r[0]), "=r"(r[1]), "=r"(r[2]), "=r"(r[3]) : "r"(addr));
}
__device__ __forceinline__ void ldsm_x2(uint32_t* r, uint32_t addr) {
    asm volatile("ldmatrix.sync.aligned.m8n8.x2.shared.b16 {%0,%1}, [%2];"
                 : "=r"(r[0]), "=r"(r[1]) : "r"(addr));
}
__device__ __forceinline__ void mma_f16(float* d, const uint32_t* a, const uint32_t* b) {
    asm volatile("mma.sync.aligned.m16n8k16.row.col.f32.f16.f16.f32 "
                 "{%0,%1,%2,%3}, {%4,%5,%6,%7}, {%8,%9}, {%0,%1,%2,%3};"
                 : "+f"(d[0]), "+f"(d[1]), "+f"(d[2]), "+f"(d[3])
                 : "r"(a[0]), "r"(a[1]), "r"(a[2]), "r"(a[3]), "r"(b[0]), "r"(b[1]));
}
__device__ __forceinline__ uint32_t packh(float lo, float hi) {
    __half2 h = __floats2half2_rn(lo, hi);       // lo -> low half
    return *(uint32_t*)&h;
}

// ==== fp16 warp-mma GEMM: D[M,N] = A'[M,KPA] @ B[N,KPA/2]^T (B wraps) =====
// A' = [ah | al] (2-term split). B chunk index wraps at NCB = (KPA/2)/64.
// CTA 128x128, 256 thr, 8 warps (2Mx4N), BK=64, 3-stage cp.async.
#define GSTAGES     3
#define STAGE_BYTES 32768
#define GSMEM_TOTAL (GSTAGES * STAGE_BYTES)

template <int EPI>
__global__ __launch_bounds__(256)
void gemm_mma_k(const __half* __restrict__ A, const __half* __restrict__ B,
                const float* __restrict__ R, float* __restrict__ C, int KPA) {
    extern __shared__ char smem[];
    uint32_t sbase = smem_to_u32(smem);
    int tid = threadIdx.x, lane = tid & 31, wid = tid >> 5;
    int wm = wid & 1, wn = wid >> 1;
    int bx = blockIdx.x, by = blockIdx.y;
    int N = gridDim.x * 128;
    int NC = KPA >> 6;                            // A chunks (64-wide)
    int NCB = NC >> 1;                            // B chunks before wrap

    const char* Ag = (const char*)(A + (size_t)(by * 128) * KPA);
    const char* Bg = (const char*)(B + (size_t)(bx * 128) * (KPA >> 1));
    size_t lda = (size_t)KPA * 2;
    size_t ldb = (size_t)KPA;                     // (KPA/2) * 2 bytes

    auto load_stage = [&](int stg, int c) {
        int cb = (c < NCB) ? c : (c - NCB);
        uint32_t sA = sbase + stg * STAGE_BYTES;
        uint32_t sB = sA + 16384;
        const char* Ac = Ag + (size_t)c * 128;
        const char* Bc = Bg + (size_t)cb * 128;
        #pragma unroll
        for (int i = 0; i < 4; i++) {
            int idx = i * 256 + tid;
            int r = idx >> 3, c16 = idx & 7;
            uint32_t dof = (uint32_t)(r * 128 + ((c16 ^ (r & 7)) << 4));
            cpasync16(sA + dof, Ac + (size_t)r * lda + c16 * 16);
            cpasync16(sB + dof, Bc + (size_t)r * ldb + c16 * 16);
        }
    };

    int aRow = lane & 15, aHi = lane >> 4;
    int bRow = lane & 7,  bHi = (lane >> 3) & 1;

    float acc[4][4][4];
    #pragma unroll
    for (int i = 0; i < 4; i++)
        #pragma unroll
        for (int j = 0; j < 4; j++)
            #pragma unroll
            for (int q = 0; q < 4; q++) acc[i][j][q] = 0.f;

    #pragma unroll
    for (int p = 0; p < GSTAGES; p++) {
        if (p < NC) load_stage(p, p);
        asm volatile("cp.async.commit_group;" ::: "memory");
    }

    for (int c = 0; c < NC; ++c) {
        int s = c % GSTAGES;
        asm volatile("cp.async.wait_group 2;" ::: "memory");
        __syncthreads();

        uint32_t sA = sbase + s * STAGE_BYTES;
        uint32_t sB = sA + 16384;
        #pragma unroll
        for (int ks = 0; ks < 4; ks++) {
            uint32_t af[4][4], bf[4][2];
            #pragma unroll
            for (int i = 0; i < 4; i++) {
                int m = wm * 64 + i * 16 + aRow;
                uint32_t addr = sA + m * 128 + (((ks * 2 + aHi) ^ (m & 7)) << 4);
                ldsm_x4(af[i], addr);
            }
            #pragma unroll
            for (int j = 0; j < 4; j++) {
                int n = wn * 32 + j * 8 + bRow;
                uint32_t addr = sB + n * 128 + (((ks * 2 + bHi) ^ (n & 7)) << 4);
                ldsm_x2(bf[j], addr);
            }
            #pragma unroll
            for (int i = 0; i < 4; i++)
                #pragma unroll
                for (int j = 0; j < 4; j++)
                    mma_f16(acc[i][j], af[i], bf[j]);
        }
        __syncthreads();
        int cn = c + GSTAGES;
        if (cn < NC) load_stage(s, cn);
        asm volatile("cp.async.commit_group;" ::: "memory");
    }

    int rowbase = by * 128 + wm * 64 + (lane >> 2);
    int colbase = bx * 128 + wn * 32 + (lane & 3) * 2;
    #pragma unroll
    for (int i = 0; i < 4; i++) {
        #pragma unroll
        for (int j = 0; j < 4; j++) {
            size_t r0 = (size_t)(rowbase + i * 16);
            int n0 = colbase + j * 8;
            float2 v0 = make_float2(acc[i][j][0], acc[i][j][1]);
            float2 v1 = make_float2(acc[i][j][2], acc[i][j][3]);
            if (EPI == 1) {
                float2 q0 = *(const float2*)(R + r0 * N + n0);
                float2 q1 = *(const float2*)(R + (r0 + 8) * N + n0);
                v0.x += q0.x; v0.y += q0.y; v1.x += q1.x; v1.y += q1.y;
            }
            *(float2*)(C + r0 * N + n0)       = v0;
            *(float2*)(C + (r0 + 8) * N + n0) = v1;
        }
    }
}

// ===== fp32 W [K][N] -> plain fp16 W^T [N][K] ====
__global__ void split_wt_k(const float* __restrict__ W, __half* __restrict__ out,
                           int K, int N, int nOfs) {
    __shared__ float tile[32][33];
    int k0 = blockIdx.y * 32, n0 = blockIdx.x * 32;
    int tx = threadIdx.x, ty = threadIdx.y;
    #pragma unroll
    for (int j = 0; j < 4; j++)
        tile[ty + 8 * j][tx] = W[(size_t)(k0 + ty + 8 * j) * N + n0 + tx];
    __syncthreads();
    #pragma unroll
    for (int j = 0; j < 4; j++) {
        int n = n0 + ty + 8 * j, k = k0 + tx;
        out[(size_t)(n + nOfs) * K + k] = __float2half(tile[tx][ty + 8 * j]);
    }
}

// ---- fused rmsnorm + 2-term split: x fp32 -> [M][2K] hi|lo fp16 ----------
__global__ void rmsnorm_split_k(const float* __restrict__ x,
                                const float* __restrict__ sc,
                                __half* __restrict__ out) {
    int row = blockIdx.x;
    int t = threadIdx.x;
    const float4* xr = (const float4*)(x + (size_t)row * C_EMB);
    const float4* s4 = (const float4*)sc;

    float4 v = xr[t];
    float ss = v.x*v.x + v.y*v.y + v.z*v.z + v.w*v.w;
    #pragma unroll
    for (int off = 16; off; off >>= 1) ss += __shfl_xor_sync(0xffffffffu, ss, off);

    __shared__ float part[8];
    __shared__ float inv_s;
    if ((t & 31) == 0) part[t >> 5] = ss;
    __syncthreads();
    if (t < 8) {
        float tot = part[t];
        #pragma unroll
        for (int off = 4; off; off >>= 1) tot += __shfl_xor_sync(0xffu, tot, off);
        if (t == 0) inv_s = rsqrtf(tot * (1.0f / C_EMB) + 1e-5f);
    }
    __syncthreads();
    float inv = inv_s;
    float4 w = s4[t];
    float a0 = v.x*inv*w.x, a1 = v.y*inv*w.y, a2 = v.z*inv*w.z, a3 = v.w*inv*w.w;

    float h0 = __half2float(__float2half(a0)), h1 = __half2float(__float2half(a1));
    float h2 = __half2float(__float2half(a2)), h3 = __half2float(__float2half(a3));
    uint2 hi = make_uint2(packh(a0, a1), packh(a2, a3));
    uint2 lo = make_uint2(packh(a0 - h0, a1 - h1), packh(a2 - h2, a3 - h3));
    char* o = (char*)(out + (size_t)row * (2 * C_EMB));
    *(uint2*)(o + t * 8)             = hi;
    *(uint2*)(o + C_EMB * 2 + t * 8) = lo;
}

// ---- fused silu-mul + 2-term split: g12 -> [M][2*NHID] hi|lo fp16 -------
__global__ void silu_split_k(const float* __restrict__ g12,
                             __half* __restrict__ out) {
    int m = blockIdx.y;
    int j = blockIdx.x * 256 + threadIdx.x;
    float a = g12[(size_t)m * (2 * NHID) + j];
    float b = g12[(size_t)m * (2 * NHID) + NHID + j];
    float v = (a / (1.f + __expf(-a))) * b;
    float h = __half2float(__float2half(v));
    __half* o = out + (size_t)m * (2 * NHID);
    o[j] = __float2half(v);
    o[NHID + j] = __float2half(v - h);
}

// ==== fused rope + split: qkv fp32 -> qs [bh][T][128] (hi|lo), ks/vs [64] ==
__global__ void qksplit_k(const float* __restrict__ qkv,
                          __half* __restrict__ qs,
                          __half* __restrict__ ks,
                          __half* __restrict__ vsp) {
    int row = blockIdx.x;
    int b = row >> 11, t = row & (T_SEQ - 1);
    int tid = threadIdx.x;
    int hh = tid >> 5, i = tid & 31;
    float theta = exp2f(-13.287712379549449f * ((float)i * (1.0f / 32.0f)));
    float ang = (float)t * theta;
    float s, c;
    sincosf(ang, &s, &c);

    const float* p = qkv + (size_t)row * (3 * C_EMB) + hh * HD + 2 * i;
    float qe = p[0], qo = p[1];
    float ke = p[C_EMB], ko = p[C_EMB + 1];
    float v0 = p[2 * C_EMB], v1 = p[2 * C_EMB + 1];
    float q0 = qe * c - qo * s, q1 = qe * s + qo * c;
    float k0 = ke * c - ko * s, k1 = ke * s + ko * c;

    size_t base = (size_t)(b * NHEAD + hh) * T_SEQ + t;
    __half* qd = qs + base * 128;
    __half* kd = ks + base * 64;
    __half* vd = vsp + base * 64;

    float qh0 = __half2float(__float2half(q0));
    float qh1 = __half2float(__float2half(q1));
    qd[2*i]      = __float2half(q0);
    qd[2*i+1]    = __float2half(q1);
    qd[64+2*i]   = __float2half(q0 - qh0);
    qd[64+2*i+1] = __float2half(q1 - qh1);

    kd[2*i]   = __float2half(k0);
    kd[2*i+1] = __float2half(k1);
    vd[2*i]   = __float2half(v0);
    vd[2*i+1] = __float2half(v1);
}

// ================= tensor-core flash attention (fp16) ======================
// Q' 2-term (128 dims), K plain (64, wrapped), V fp16.
// Writes [M][2*C_EMB] hi|lo split of y directly (feeds attn-proj GEMM).
#define A_QS   0
#define A_KS   17408
#define A_VS   35840
#define A_YM   54272
#define ASMEM  54528

__global__ __launch_bounds__(128)
void attn_mma_k(const __half* __restrict__ qs,
                const __half* __restrict__ ks,
                const __half* __restrict__ vs,
                const int* __restrict__ ymask,
                __half* __restrict__ yab) {
    extern __shared__ char smem[];
    uint32_t sb = smem_to_u32(smem);
    int tid = threadIdx.x, lane = tid & 31, wid = tid >> 5;
    int bx = (gridDim.x - 1) - blockIdx.x;
    int bh = blockIdx.y;
    int b = bh >> 4, head = bh & 15;
    int* ymsm = (int*)(smem + A_YM);

    const char* qg = (const char*)(qs + ((size_t)bh * T_SEQ + bx * 64) * 128);
    const char* kg = (const char*)(ks + (size_t)bh * T_SEQ * 64);
    const char* vg = (const char*)(vs + (size_t)bh * T_SEQ * 64);

    if (tid < 64) ymsm[tid] = ymask[b * 64 + tid];

    // Q tile: 64 rows x 256B, row stride 272
    #pragma unroll
    for (int Lb = 0; Lb < 1024; Lb += 128) {
        int L = Lb + tid;
        int r = L >> 4, c = L & 15;
        cpasync16(sb + A_QS + r * 272 + c * 16, qg + (size_t)r * 256 + c * 16);
    }
    asm volatile("cp.async.commit_group;" ::: "memory");

    auto load_kv = [&](int stg, int kt) {
        uint32_t kd = sb + A_KS + stg * 9216;
        uint32_t vd = sb + A_VS + stg * 9216;
        const char* kc = kg + (size_t)(kt * 64) * 128;
        const char* vc = vg + (size_t)(kt * 64) * 128;
        #pragma unroll
        for (int Lb = 0; Lb < 512; Lb += 128) {
            int L = Lb + tid;
            int r = L >> 3, c = L & 7;
            cpasync16(kd + r * 144 + c * 16, kc + (size_t)r * 128 + c * 16);
            cpasync16(vd + r * 144 + c * 16, vc + (size_t)r * 128 + c * 16);
        }
    };

    load_kv(0, 0);
    asm volatile("cp.async.commit_group;" ::: "memory");

    asm volatile("cp.async.wait_group 1;" ::: "memory");
    __syncthreads();
    uint32_t qf[8][4];
    {
        int arow = wid * 16 + (lane & 15);
        int ahi  = lane >> 4;
        #pragma unroll
        for (int kk = 0; kk < 8; kk++) {
            uint32_t addr = sb + A_QS + arow * 272 + (kk * 16 + ahi * 8) * 2;
            ldsm_x4(qf[kk], addr);
        }
    }

    float o[8][4];
    #pragma unroll
    for (int j = 0; j < 8; j++)
        #pragma unroll
        for (int q = 0; q < 4; q++) o[j][q] = 0.f;
    float mA = -1e30f, mB = -1e30f, lA = 0.f, lB = 0.f;

    int rloc = wid * 16 + (lane >> 2);
    int gA = bx * 64 + rloc, gB = gA + 8;
    int ymA = 0, ymB = 0;
    __syncthreads();
    if (bx == 0) { ymA = ymsm[rloc]; ymB = ymsm[rloc + 8]; }

    int ntiles = bx + 1;
    int s = 0;
    for (int kt = 0; kt < ntiles; kt++) {
        if (kt + 1 < ntiles) {
            load_kv(s ^ 1, kt + 1);
            asm volatile("cp.async.commit_group;" ::: "memory");
            asm volatile("cp.async.wait_group 1;" ::: "memory");
        } else {
            asm volatile("cp.async.wait_group 0;" ::: "memory");
        }
        __syncthreads();

        uint32_t kds = sb + A_KS + s * 9216;
        uint32_t vds = sb + A_VS + s * 9216;

        float sf[8][4];
        #pragma unroll
        for (int j = 0; j < 8; j++)
            #pragma unroll
            for (int q = 0; q < 4; q++) sf[j][q] = 0.f;

        #pragma unroll
        for (int kk = 0; kk < 8; kk++) {
            int kc = kk & 3;                      // K wraps: q chunk kk uses k chunk kk%4
            uint32_t kb[8][2];
            #pragma unroll
            for (int jp = 0; jp < 4; jp++) {
                int n = jp * 16 + (lane & 7) + ((lane >> 4) & 1) * 8;
                uint32_t addr = kds + n * 144 + (kc * 16 + ((lane >> 3) & 1) * 8) * 2;
                uint32_t rr[4];
                ldsm_x4(rr, addr);
                kb[jp*2][0] = rr[0]; kb[jp*2][1] = rr[1];
                kb[jp*2+1][0] = rr[2]; kb[jp*2+1][1] = rr[3];
            }
            #pragma unroll
            for (int j = 0; j < 8; j++) mma_f16(sf[j], qf[kk], kb[j]);
        }

        bool diag = (kt == bx);
        int colb = (lane & 3) * 2;
        #pragma unroll
        for (int j = 0; j < 8; j++) {
            #pragma unroll
            for (int c = 0; c < 2; c++) {
                float vA = sf[j][c] * 0.125f;
                float vB = sf[j][c + 2] * 0.125f;
                if (diag) {
                    int gc = kt * 64 + j * 8 + colb + c;
                    int ymc = (bx == 0) ? ymsm[gc & 63] : 0;
                    if (!((gc <= gA) || (ymA && ymc))) vA = -1e30f;
                    if (!((gc <= gB) || (ymB && ymc))) vB = -1e30f;
                }
                sf[j][c] = vA; sf[j][c + 2] = vB;
            }
        }
        float nmA = mA, nmB = mB;
        #pragma unroll
        for (int j = 0; j < 8; j++) {
            nmA = fmaxf(nmA, fmaxf(sf[j][0], sf[j][1]));
            nmB = fmaxf(nmB, fmaxf(sf[j][2], sf[j][3]));
        }
        nmA = fmaxf(nmA, __shfl_xor_sync(0xffffffffu, nmA, 1));
        nmA = fmaxf(nmA, __shfl_xor_sync(0xffffffffu, nmA, 2));
        nmB = fmaxf(nmB, __shfl_xor_sync(0xffffffffu, nmB, 1));
        nmB = fmaxf(nmB, __shfl_xor_sync(0xffffffffu, nmB, 2));

        float corrA = __expf(mA - nmA), corrB = __expf(mB - nmB);
        mA = nmA; mB = nmB;
        float sumA = 0.f, sumB = 0.f;
        #pragma unroll
        for (int j = 0; j < 8; j++) {
            float p0 = __expf(sf[j][0] - nmA);
            float p1 = __expf(sf[j][1] - nmA);
            float p2 = __expf(sf[j][2] - nmB);
            float p3 = __expf(sf[j][3] - nmB);
            sumA += p0 + p1; sumB += p2 + p3;
            sf[j][0] = p0; sf[j][1] = p1; sf[j][2] = p2; sf[j][3] = p3;
        }
        sumA += __shfl_xor_sync(0xffffffffu, sumA, 1);
        sumA += __shfl_xor_sync(0xffffffffu, sumA, 2);
        sumB += __shfl_xor_sync(0xffffffffu, sumB, 1);
        sumB += __shfl_xor_sync(0xffffffffu, sumB, 2);
        lA = lA * corrA + sumA;
        lB = lB * corrB + sumB;
        #pragma unroll
        for (int j = 0; j < 8; j++) {
            o[j][0] *= corrA; o[j][1] *= corrA;
            o[j][2] *= corrB; o[j][3] *= corrB;
        }

        uint32_t pf[4][4];
        #pragma unroll
        for (int kk2 = 0; kk2 < 4; kk2++) {
            int j0 = 2 * kk2, j1 = j0 + 1;
            pf[kk2][0] = packh(sf[j0][0], sf[j0][1]);
            pf[kk2][1] = packh(sf[j0][2], sf[j0][3]);
            pf[kk2][2] = packh(sf[j1][0], sf[j1][1]);
            pf[kk2][3] = packh(sf[j1][2], sf[j1][3]);
        }

        #pragma unroll
        for (int kk2 = 0; kk2 < 4; kk2++) {
            #pragma unroll
            for (int jdp = 0; jdp < 4; jdp++) {
                int key = kk2 * 16 + ((lane >> 3) & 1) * 8 + (lane & 7);
                int dim = (jdp * 2 + (lane >> 4)) * 8;
                uint32_t rr[4];
                ldsm_x4t(rr, vds + key * 144 + dim * 2);
                mma_f16(o[jdp * 2],     pf[kk2], rr);
                mma_f16(o[jdp * 2 + 1], pf[kk2], rr + 2);
            }
        }

        __syncthreads();
        s ^= 1;
    }

    // ---- epilogue: write hi|lo split of y directly ----
    float iA = 1.f / lA, iB = 1.f / lB;
    int col0 = head * 64 + (lane & 3) * 2;
    size_t rowA = (size_t)(b * T_SEQ + gA);
    size_t rowB = rowA + 8;
    #pragma unroll
    for (int jd = 0; jd < 8; jd++) {
        float a0 = o[jd][0] * iA, a1 = o[jd][1] * iA;
        float b0 = o[jd][2] * iB, b1 = o[jd][3] * iB;
        float ha0 = __half2float(__float2half(a0)), ha1 = __half2float(__float2half(a1));
        float hb0 = __half2float(__float2half(b0)), hb1 = __half2float(__float2half(b1));
        uint32_t hiA = packh(a0, a1), hiB = packh(b0, b1);
        uint32_t loA = packh(a0 - ha0, a1 - ha1);
        uint32_t loB = packh(b0 - hb0, b1 - hb1);
        uint32_t* pA = (uint32_t*)(yab + rowA * (2 * C_EMB) + col0 + jd * 8);
        uint32_t* pB = (uint32_t*)(yab + rowB * (2 * C_EMB) + col0 + jd * 8);
        pA[0] = hiA; pA[C_EMB / 2] = loA;
        pB[0] = hiB; pB[C_EMB / 2] = loB;
    }
}

// ---------------- driver ----------------
extern "C" void kernel_launch(void* const* d_in, const int* in_sizes, int n_in,
                              void* d_out, int out_size) {
    const float* x      = (const float*)d_in[0];
    const int*   ymask  = (const int*)  d_in[1];
    const float* Wqkv   = (const float*)d_in[2];
    const float* Wattn  = (const float*)d_in[3];
    const float* scale1 = (const float*)d_in[4];
    const float* scale2 = (const float*)d_in[5];
    const float* Wfc1   = (const float*)d_in[6];
    const float* Wfc2   = (const float*)d_in[7];
    const float* Wmlp   = (const float*)d_in[8];
    float* out = (float*)d_out;

    float *qkv, *x2, *g12;
    __half *ab, *bb, *qsp, *ksp, *vsp;
    cudaGetSymbolAddress((void**)&qkv, g_qkv);
    cudaGetSymbolAddress((void**)&x2,  g_x2);
    cudaGetSymbolAddress((void**)&g12, g_g12);
    cudaGetSymbolAddress((void**)&ab,  g_abuf);
    cudaGetSymbolAddress((void**)&bb,  g_bbuf);
    cudaGetSymbolAddress((void**)&qsp, g_qs);
    cudaGetSymbolAddress((void**)&ksp, g_ks);
    cudaGetSymbolAddress((void**)&vsp, g_vs);

    cudaFuncSetAttribute(gemm_mma_k<0>, cudaFuncAttributeMaxDynamicSharedMemorySize, GSMEM_TOTAL);
    cudaFuncSetAttribute(gemm_mma_k<1>, cudaFuncAttributeMaxDynamicSharedMemorySize, GSMEM_TOTAL);
    cudaFuncSetAttribute(attn_mma_k,    cudaFuncAttributeMaxDynamicSharedMemorySize, ASMEM);

    dim3 wt8(32, 8);

    // ---- ab = split2(rmsnorm(x));  qkv = ab @ Wqkv' ----
    rmsnorm_split_k<<<TOK, 256>>>(x, scale1, ab);
    split_wt_k<<<dim3(3*C_EMB/32, C_EMB/32), wt8>>>(Wqkv, bb, C_EMB, 3*C_EMB, 0);
    gemm_mma_k<0><<<dim3(3*C_EMB/128, TOK/128), 256, GSMEM_TOTAL>>>(ab, bb, nullptr, qkv, 2*C_EMB);

    // ---- rope+split -> attention (writes split of y into ab) ----
    qksplit_k<<<TOK, 512>>>(qkv, qsp, ksp, vsp);
    attn_mma_k<<<dim3(T_SEQ/64, BATCH*NHEAD), 128, ASMEM>>>(qsp, ksp, vsp, ymask, ab);

    // ---- x2 = x + y @ Wattn ----
    split_wt_k<<<dim3(C_EMB/32, C_EMB/32), wt8>>>(Wattn, bb, C_EMB, C_EMB, 0);
    gemm_mma_k<1><<<dim3(C_EMB/128, TOK/128), 256, GSMEM_TOTAL>>>(ab, bb, x, x2, 2*C_EMB);

    // ---- ab = split2(rmsnorm(x2));  g12 = ab @ [Wfc1|Wfc2]' ----
    rmsnorm_split_k<<<TOK, 256>>>(x2, scale2, ab);
    split_wt_k<<<dim3(NHID/32, C_EMB/32), wt8>>>(Wfc1, bb, C_EMB, NHID, 0);
    split_wt_k<<<dim3(NHID/32, C_EMB/32), wt8>>>(Wfc2, bb, C_EMB, NHID, NHID);
    gemm_mma_k<0><<<dim3(2*NHID/128, TOK/128), 256, GSMEM_TOTAL>>>(ab, bb, nullptr, g12, 2*C_EMB);

    // ---- ab = split2(silu(g1)*g2);  out = x2 + ab @ Wmlp' ----
    silu_split_k<<<dim3(NHID/256, TOK), 256>>>(g12, ab);
    split_wt_k<<<dim3(C_EMB/32, NHID/32), wt8>>>(Wmlp, bb, NHID, C_EMB, 0);
    gemm_mma_k<1><<<dim3(C_EMB/128, TOK/128), 256, GSMEM_TOTAL>>>(ab, bb, x2, out, 2*NHID);
}